// round 1
// baseline (speedup 1.0000x reference)
#include <cuda_runtime.h>

#define DECAY 0.99f
#define ONE_MINUS_DECAY 0.01f
#define EPSF 1e-5f
#define D 512
#define KCODES 1024
#define NROWS 65536

// ---------------- device scratch (no allocations allowed) ----------------
__device__ float g_e2[KCODES];
__device__ float g_counts[KCODES];
__device__ float g_embed_sum[KCODES * D];
__device__ int   g_ind[NROWS];
__device__ float g_cs[KCODES];

// ---------------- zero the scatter accumulators ----------------
__global__ void zero_scratch() {
    int i = blockIdx.x * blockDim.x + threadIdx.x;
    if (i < KCODES) g_counts[i] = 0.0f;
    if (i < KCODES * D) g_embed_sum[i] = 0.0f;
}

// ---------------- |e_k|^2 per code ----------------
__global__ void compute_e2(const float* __restrict__ embed) {
    int k = blockIdx.x;
    int lane = threadIdx.x;  // 128 threads, one float4 each (D/4 = 128)
    const float4* e = (const float4*)(embed + (size_t)k * D);
    float4 v = e[lane];
    float s = v.x * v.x + v.y * v.y + v.z * v.z + v.w * v.w;
#pragma unroll
    for (int off = 16; off; off >>= 1) s += __shfl_down_sync(0xffffffffu, s, off);
    __shared__ float sh[4];
    if ((lane & 31) == 0) sh[lane >> 5] = s;
    __syncthreads();
    if (lane == 0) g_e2[k] = sh[0] + sh[1] + sh[2] + sh[3];
}

// ---------------- fused score GEMM + argmax ----------------
// scores[n][k] = 2 * dot(x[n], e[k]) - |e_k|^2 ; argmax over k, tie -> lowest k.
// Tiling: BM=128 rows, BN=64 codes per tile (loop over K), BK=16, 256 threads,
// 8x4 register microtile per thread.
__global__ __launch_bounds__(256) void gemm_argmax(
    const float* __restrict__ x, const float* __restrict__ embed) {
    __shared__ float As[16][128];
    __shared__ float Bs[16][64];

    int tid = threadIdx.x;
    int tx = tid & 15;   // column group (4 cols each)
    int ty = tid >> 4;   // row group (8 rows each)
    int rowBase = blockIdx.x * 128;

    float bestVal[8];
    int bestIdx[8];
#pragma unroll
    for (int i = 0; i < 8; i++) { bestVal[i] = -3.4e38f; bestIdx[i] = 0; }

    int lr = tid >> 2;          // 0..63
    int lc = (tid & 3) << 2;    // 0,4,8,12

    for (int kt = 0; kt < KCODES; kt += 64) {
        float acc[8][4];
#pragma unroll
        for (int i = 0; i < 8; i++)
#pragma unroll
            for (int j = 0; j < 4; j++) acc[i][j] = 0.0f;

        for (int dt = 0; dt < D; dt += 16) {
            // issue global loads before the barrier so they overlap the wait
            float4 va0 = *(const float4*)(x + (size_t)(rowBase + lr) * D + dt + lc);
            float4 va1 = *(const float4*)(x + (size_t)(rowBase + lr + 64) * D + dt + lc);
            float4 vb  = *(const float4*)(embed + (size_t)(kt + lr) * D + dt + lc);

            __syncthreads();  // previous tile's compute done
            As[lc + 0][lr] = va0.x; As[lc + 1][lr] = va0.y;
            As[lc + 2][lr] = va0.z; As[lc + 3][lr] = va0.w;
            As[lc + 0][lr + 64] = va1.x; As[lc + 1][lr + 64] = va1.y;
            As[lc + 2][lr + 64] = va1.z; As[lc + 3][lr + 64] = va1.w;
            Bs[lc + 0][lr] = vb.x; Bs[lc + 1][lr] = vb.y;
            Bs[lc + 2][lr] = vb.z; Bs[lc + 3][lr] = vb.w;
            __syncthreads();

#pragma unroll
            for (int kk = 0; kk < 16; kk++) {
                float4 a0 = *(const float4*)&As[kk][ty * 8];
                float4 a1 = *(const float4*)&As[kk][ty * 8 + 4];
                float4 b  = *(const float4*)&Bs[kk][tx * 4];
                float ar[8] = {a0.x, a0.y, a0.z, a0.w, a1.x, a1.y, a1.z, a1.w};
                float br[4] = {b.x, b.y, b.z, b.w};
#pragma unroll
                for (int i = 0; i < 8; i++)
#pragma unroll
                    for (int j = 0; j < 4; j++)
                        acc[i][j] = fmaf(ar[i], br[j], acc[i][j]);
            }
        }

        // epilogue for this K tile: score = 2*dot - |e|^2, keep running argmax
#pragma unroll
        for (int j = 0; j < 4; j++) {
            int col = kt + tx * 4 + j;
            float c2 = g_e2[col];
#pragma unroll
            for (int i = 0; i < 8; i++) {
                float s = 2.0f * acc[i][j] - c2;
                if (s > bestVal[i]) { bestVal[i] = s; bestIdx[i] = col; }
            }
        }
    }

    // cross-thread argmax across the 16 column-threads of each row (same ty).
    // lanes (ty&1)*16 + tx within the warp; xor offsets < 16 stay in-group.
#pragma unroll
    for (int i = 0; i < 8; i++) {
        float v = bestVal[i];
        int id = bestIdx[i];
#pragma unroll
        for (int off = 8; off >= 1; off >>= 1) {
            float ov = __shfl_xor_sync(0xffffffffu, v, off);
            int oi = __shfl_xor_sync(0xffffffffu, id, off);
            if (ov > v || (ov == v && oi < id)) { v = ov; id = oi; }
        }
        if (tx == 0) g_ind[rowBase + ty * 8 + i] = id;
    }
}

// ---------------- gather quantize + scatter counts/embed_sum ----------------
__global__ void gather_scatter(const float* __restrict__ x,
                               const float* __restrict__ embed,
                               float* __restrict__ quant,
                               float* __restrict__ eind) {
    int row = blockIdx.x;
    int k = g_ind[row];
    if (threadIdx.x == 0) {
        atomicAdd(&g_counts[k], 1.0f);
        eind[row] = (float)k;
    }
    int c = threadIdx.x;  // 128 threads -> one float4 each
    float4 ev = *(const float4*)(embed + (size_t)k * D + c * 4);
    *(float4*)(quant + (size_t)row * D + c * 4) = ev;
    float4 xv = *(const float4*)(x + (size_t)row * D + c * 4);
    float* es = g_embed_sum + (size_t)k * D + c * 4;
    atomicAdd(es + 0, xv.x);
    atomicAdd(es + 1, xv.y);
    atomicAdd(es + 2, xv.z);
    atomicAdd(es + 3, xv.w);
}

// ---------------- EMA cluster size + laplace-smoothed denominator ----------------
__global__ void ema_cs(const float* __restrict__ cluster_size,
                       float* __restrict__ ncs_out) {
    int k = threadIdx.x;  // 1024 threads, one block
    float ncs = cluster_size[k] * DECAY + ONE_MINUS_DECAY * g_counts[k];
    ncs_out[k] = ncs;
    __shared__ float sh[1024];
    sh[k] = ncs;
    __syncthreads();
#pragma unroll
    for (int s = 512; s > 0; s >>= 1) {
        if (k < s) sh[k] += sh[k + s];
        __syncthreads();
    }
    float n = sh[0];
    float cs = (ncs + EPSF) / (n + (float)KCODES * EPSF) * n;
    g_cs[k] = cs;
}

// ---------------- EMA embed_avg + normalized embed ----------------
__global__ void ema_embed(const float* __restrict__ embed_avg,
                          float* __restrict__ nea_out,
                          float* __restrict__ ne_out) {
    int idx = blockIdx.x * blockDim.x + threadIdx.x;
    if (idx >= KCODES * D) return;
    float nea = embed_avg[idx] * DECAY + ONE_MINUS_DECAY * g_embed_sum[idx];
    nea_out[idx] = nea;
    ne_out[idx] = nea / g_cs[idx >> 9];  // idx / D
}

// ---------------- launch ----------------
extern "C" void kernel_launch(void* const* d_in, const int* in_sizes, int n_in,
                              void* d_out, int out_size) {
    const float* x = (const float*)d_in[0];
    const float* embed = (const float*)d_in[1];
    const float* cluster_size = (const float*)d_in[2];
    const float* embed_avg = (const float*)d_in[3];

    float* out = (float*)d_out;
    float* quant = out;                                  // 65536*512
    float* eind  = quant + (size_t)NROWS * D;            // 65536
    float* ncs   = eind + NROWS;                         // 1024
    float* nea   = ncs + KCODES;                         // 1024*512
    float* ne    = nea + (size_t)KCODES * D;             // 1024*512

    zero_scratch<<<(KCODES * D + 255) / 256, 256>>>();
    compute_e2<<<KCODES, 128>>>(embed);
    gemm_argmax<<<NROWS / 128, 256>>>(x, embed);
    gather_scatter<<<NROWS, 128>>>(x, embed, quant, eind);
    ema_cs<<<1, 1024>>>(cluster_size, ncs);
    ema_embed<<<(KCODES * D + 255) / 256, 256>>>(embed_avg, nea, ne);
}

// round 4
// speedup vs baseline: 1.5797x; 1.5797x over previous
#include <cuda_runtime.h>
#include <cuda_bf16.h>
#include <cstdint>

#define DECAY 0.99f
#define ONE_MINUS_DECAY 0.01f
#define EPSF 1e-5f
#define D 512
#define KCODES 1024
#define NROWS 65536
#define ROWTILES (NROWS / 128)   // 512
#define NTILES 128               // 8 n-chunks * 16 k-tiles
#define STAGE_BYTES 32768        // Ah/Al/Bh/Bl each 128x32 bf16 = 8KB
#define SMEM_TOTAL (3 * STAGE_BYTES)

// ---------------- device scratch (bf16 pairs packed in uint) ----------------
__device__ unsigned g_xhi[NROWS * D / 2];
__device__ unsigned g_xlo[NROWS * D / 2];
__device__ unsigned g_bhi[KCODES * D / 2];
__device__ unsigned g_blo[KCODES * D / 2];
__device__ float g_e2h[KCODES];   // 0.5*|e|^2
__device__ float g_counts[KCODES];
__device__ float g_embed_sum[KCODES * D];
__device__ int   g_ind[NROWS];
__device__ float g_cs[KCODES];
__device__ int   g_flag[NROWS];
__device__ int   g_nflag;

// ---------------- PTX helpers (all baseline sm_80/90, no 'a' features) -----
__device__ __forceinline__ uint32_t smem_u32(const void* p) {
    uint32_t a;
    asm("{ .reg .u64 t; cvta.to.shared.u64 t, %1; cvt.u32.u64 %0, t; }" : "=r"(a) : "l"(p));
    return a;
}
#define CP_ASYNC16(soff, gptr) \
    asm volatile("cp.async.cg.shared.global [%0], [%1], 16;" \
                 :: "r"(soff), "l"(__cvta_generic_to_global(gptr)))
#define CP_COMMIT() asm volatile("cp.async.commit_group;" ::: "memory")
#define CP_WAIT1() asm volatile("cp.async.wait_group 1;" ::: "memory")

#define LDMX4(r, addr) \
    asm volatile("ldmatrix.sync.aligned.m8n8.x4.shared.b16 {%0,%1,%2,%3}, [%4];" \
                 : "=r"((r)[0]), "=r"((r)[1]), "=r"((r)[2]), "=r"((r)[3]) : "r"(addr))

#define MMA_BF16(c, a, b0, b1) \
    asm volatile("mma.sync.aligned.m16n8k16.row.col.f32.bf16.bf16.f32 " \
                 "{%0,%1,%2,%3}, {%4,%5,%6,%7}, {%8,%9}, {%0,%1,%2,%3};" \
                 : "+f"((c)[0]), "+f"((c)[1]), "+f"((c)[2]), "+f"((c)[3]) \
                 : "r"((a)[0]), "r"((a)[1]), "r"((a)[2]), "r"((a)[3]), "r"(b0), "r"(b1))

// ---------------- zero + prep ----------------
__global__ void zero_scratch() {
    int i = blockIdx.x * blockDim.x + threadIdx.x;
    if (i < KCODES) g_counts[i] = 0.0f;
    if (i < KCODES * D) g_embed_sum[i] = 0.0f;
    if (i == 0) g_nflag = 0;
}

__global__ void compute_e2h(const float* __restrict__ embed) {
    int k = blockIdx.x;
    int lane = threadIdx.x;
    const float4* e = (const float4*)(embed + (size_t)k * D);
    float4 v = e[lane];
    float s = v.x * v.x + v.y * v.y + v.z * v.z + v.w * v.w;
#pragma unroll
    for (int off = 16; off; off >>= 1) s += __shfl_down_sync(0xffffffffu, s, off);
    __shared__ float sh[4];
    if ((lane & 31) == 0) sh[lane >> 5] = s;
    __syncthreads();
    if (lane == 0) g_e2h[k] = 0.5f * (sh[0] + sh[1] + sh[2] + sh[3]);
}

// ---------------- split-bf16 conversion (plain row-major) ----------------
__device__ __forceinline__ unsigned pack2(float a, float b) {
    unsigned lo = __bfloat16_as_ushort(__float2bfloat16(a));
    unsigned hi = __bfloat16_as_ushort(__float2bfloat16(b));
    return lo | (hi << 16);
}

__global__ void convert_x(const float* __restrict__ x) {
    size_t i = (size_t)blockIdx.x * blockDim.x + threadIdx.x;  // NROWS*D/2 threads
    float2 v = *(const float2*)(x + i * 2);
    float h0 = __bfloat162float(__float2bfloat16(v.x));
    float h1 = __bfloat162float(__float2bfloat16(v.y));
    g_xhi[i] = pack2(v.x, v.y);
    g_xlo[i] = pack2(v.x - h0, v.y - h1);
}

__global__ void convert_b(const float* __restrict__ embed) {
    size_t i = (size_t)blockIdx.x * blockDim.x + threadIdx.x;  // KCODES*D/2 threads
    float2 v = *(const float2*)(embed + i * 2);
    float h0 = __bfloat162float(__float2bfloat16(v.x));
    float h1 = __bfloat162float(__float2bfloat16(v.y));
    g_bhi[i] = pack2(v.x, v.y);
    g_blo[i] = pack2(v.x - h0, v.y - h1);
}

// ---------------- HMMA GEMM + fused argmax ----------------
// Block: 256 thr, warps 2(M) x 4(N). Block tile 128x128, BK=32 bf16.
// Loops all 8 N-chunks inside the block with running best/second/argmax.
__global__ void __launch_bounds__(256, 1) gemm_hmma() {
    extern __shared__ char smem[];
    uint32_t sb = smem_u32(smem);
    const int tid = threadIdx.x;
    const int lane = tid & 31;
    const int warpM = (tid >> 5) >> 2;   // 0..1
    const int warpN = (tid >> 5) & 3;    // 0..3
    const int gid = lane >> 2, tig = lane & 3;
    const int rowTile = blockIdx.x;

    float acc[4][4][4];
    float best[8], second[8];
    int bidx[8];
#pragma unroll
    for (int s = 0; s < 8; s++) { best[s] = -3.4e38f; second[s] = -3.4e38f; bidx[s] = 0; }

    // ---- cp.async issue for tile t (nc = t>>4, kt = t&15) ----
    auto issue = [&](int t) {
        int nc = t >> 4, kt = t & 15;
        uint32_t st = sb + (t % 3) * STAGE_BYTES;
#pragma unroll
        for (int i = 0; i < 8; i++) {
            int idx = tid + i * 256;           // 0..2047
            int mat = idx >> 9;                // 0 Ah, 1 Al, 2 Bh, 3 Bl
            int id2 = idx & 511;
            int row = id2 >> 2, c = id2 & 3;
            uint32_t soff = st + mat * 8192 + row * 64 + ((c ^ ((row >> 1) & 3)) << 4);
            size_t goff = (mat < 2)
                ? ((size_t)(rowTile * 128 + row) * D + kt * 32 + c * 8) >> 1
                : ((size_t)(nc * 128 + row) * D + kt * 32 + c * 8) >> 1;
            const unsigned* gp =
                (mat == 0) ? g_xhi + goff :
                (mat == 1) ? g_xlo + goff :
                (mat == 2) ? g_bhi + goff : g_blo + goff;
            CP_ASYNC16(soff, gp);
        }
        CP_COMMIT();
    };

    issue(0); issue(1);

    for (int t = 0; t < NTILES; t++) {
        CP_WAIT1();
        __syncthreads();
        if (t + 2 < NTILES) issue(t + 2); else CP_COMMIT();

        if ((t & 15) == 0) {
#pragma unroll
            for (int m = 0; m < 4; m++)
#pragma unroll
                for (int n = 0; n < 4; n++)
#pragma unroll
                    for (int j = 0; j < 4; j++) acc[m][n][j] = 0.0f;
        }

        uint32_t st = sb + (t % 3) * STAGE_BYTES;
#pragma unroll
        for (int ks = 0; ks < 2; ks++) {
            uint32_t ah[4][4], al[4][4], bh[2][4], bl[2][4];
#pragma unroll
            for (int m = 0; m < 4; m++) {
                int r = warpM * 64 + m * 16 + (lane & 15);
                int kc = ks * 2 + (lane >> 4);
                uint32_t a = st + r * 64 + ((kc ^ ((r >> 1) & 3)) << 4);
                LDMX4(ah[m], a);
                LDMX4(al[m], a + 8192);
            }
#pragma unroll
            for (int p = 0; p < 2; p++) {
                int grp = lane >> 3;
                int nt = p * 2 + (grp >> 1);
                int kc = ks * 2 + (grp & 1);
                int r = warpN * 32 + nt * 8 + (lane & 7);
                uint32_t a = st + 2 * 8192 + r * 64 + ((kc ^ ((r >> 1) & 3)) << 4);
                LDMX4(bh[p], a);
                LDMX4(bl[p], a + 8192);
            }
#pragma unroll
            for (int m = 0; m < 4; m++)
#pragma unroll
                for (int n = 0; n < 4; n++) {
                    uint32_t b0h = bh[n >> 1][(n & 1) * 2], b1h = bh[n >> 1][(n & 1) * 2 + 1];
                    uint32_t b0l = bl[n >> 1][(n & 1) * 2], b1l = bl[n >> 1][(n & 1) * 2 + 1];
                    MMA_BF16(acc[m][n], ah[m], b0h, b1h);
                    MMA_BF16(acc[m][n], ah[m], b0l, b1l);
                    MMA_BF16(acc[m][n], al[m], b0h, b1h);
                }
        }

        if ((t & 15) == 15) {
            int nc = t >> 4;
#pragma unroll
            for (int n = 0; n < 4; n++) {
                int col0 = nc * 128 + warpN * 32 + n * 8 + tig * 2;
                float e0 = __ldg(&g_e2h[col0]);
                float e1 = __ldg(&g_e2h[col0 + 1]);
#pragma unroll
                for (int m = 0; m < 4; m++)
#pragma unroll
                    for (int h = 0; h < 2; h++) {
                        int slot = m * 2 + h;
                        float s0 = acc[m][n][h * 2 + 0] - e0;
                        float s1 = acc[m][n][h * 2 + 1] - e1;
                        if (s0 > best[slot]) { second[slot] = best[slot]; best[slot] = s0; bidx[slot] = col0; }
                        else if (s0 > second[slot]) second[slot] = s0;
                        if (s1 > best[slot]) { second[slot] = best[slot]; best[slot] = s1; bidx[slot] = col0 + 1; }
                        else if (s1 > second[slot]) second[slot] = s1;
                    }
            }
        }
    }

    // ---- merge: across tig lanes (same row, different cols) ----
    __syncthreads();  // pipeline done; smem reusable
    float* mb = (float*)smem;          // [128][4]
    float* ms = mb + 512;
    int*   mi = (int*)(ms + 512);
#pragma unroll
    for (int slot = 0; slot < 8; slot++) {
        float b = best[slot], s = second[slot];
        int i = bidx[slot];
#pragma unroll
        for (int off = 1; off <= 2; off <<= 1) {
            float ob = __shfl_xor_sync(0xffffffffu, b, off);
            float os = __shfl_xor_sync(0xffffffffu, s, off);
            int   oi = __shfl_xor_sync(0xffffffffu, i, off);
            if (ob > b || (ob == b && oi < i)) { s = fmaxf(os, b); b = ob; i = oi; }
            else s = fmaxf(s, ob);
        }
        if (tig == 0) {
            int row = warpM * 64 + (slot >> 1) * 16 + gid + (slot & 1) * 8;
            mb[row * 4 + warpN] = b; ms[row * 4 + warpN] = s; mi[row * 4 + warpN] = i;
        }
    }
    __syncthreads();
    if (tid < 128) {
        int row = tid;
        float b = mb[row * 4], s = ms[row * 4];
        int i = mi[row * 4];
#pragma unroll
        for (int w = 1; w < 4; w++) {
            float ob = mb[row * 4 + w], os = ms[row * 4 + w];
            int oi = mi[row * 4 + w];
            if (ob > b || (ob == b && oi < i)) { s = fmaxf(os, b); b = ob; i = oi; }
            else s = fmaxf(s, ob);
        }
        int grow = rowTile * 128 + row;
        g_ind[grow] = i;
        if (b - s < 0.02f) {
            int p = atomicAdd(&g_nflag, 1);
            g_flag[p] = grow;
        }
    }
}

// ---------------- exact fp32 rescue for low-margin rows ----------------
__global__ void __launch_bounds__(256) rescue(const float* __restrict__ x,
                                              const float* __restrict__ embed) {
    __shared__ float xr[D];
    __shared__ float bv[256];
    __shared__ int   bidx[256];
    int tid = threadIdx.x;
    int nf = g_nflag;
    for (int fi = blockIdx.x; fi < nf; fi += gridDim.x) {
        int row = g_flag[fi];
        __syncthreads();
        for (int i = tid; i < D; i += 256) xr[i] = x[(size_t)row * D + i];
        __syncthreads();
        float best = -3.4e38f;
        int bi = 0;
        for (int c = tid; c < KCODES; c += 256) {
            const float* e = embed + (size_t)c * D;
            float d = 0.0f;
#pragma unroll 8
            for (int j = 0; j < D; j++) d = fmaf(xr[j], e[j], d);
            float s = d - g_e2h[c];
            if (s > best) { best = s; bi = c; }
        }
        bv[tid] = best; bidx[tid] = bi;
        __syncthreads();
        for (int s = 128; s > 0; s >>= 1) {
            if (tid < s) {
                if (bv[tid + s] > bv[tid] ||
                    (bv[tid + s] == bv[tid] && bidx[tid + s] < bidx[tid])) {
                    bv[tid] = bv[tid + s]; bidx[tid] = bidx[tid + s];
                }
            }
            __syncthreads();
        }
        if (tid == 0) g_ind[row] = bidx[0];
        __syncthreads();
    }
}

// ---------------- gather quantize + scatter counts/embed_sum ----------------
__global__ void gather_scatter(const float* __restrict__ x,
                               const float* __restrict__ embed,
                               float* __restrict__ quant,
                               float* __restrict__ eind) {
    int row = blockIdx.x;
    int k = g_ind[row];
    if (threadIdx.x == 0) {
        atomicAdd(&g_counts[k], 1.0f);
        eind[row] = (float)k;
    }
    int c = threadIdx.x;
    float4 ev = *(const float4*)(embed + (size_t)k * D + c * 4);
    *(float4*)(quant + (size_t)row * D + c * 4) = ev;
    float4 xv = *(const float4*)(x + (size_t)row * D + c * 4);
    float* es = g_embed_sum + (size_t)k * D + c * 4;
    atomicAdd(es + 0, xv.x);
    atomicAdd(es + 1, xv.y);
    atomicAdd(es + 2, xv.z);
    atomicAdd(es + 3, xv.w);
}

// ---------------- EMA epilogues ----------------
__global__ void ema_cs(const float* __restrict__ cluster_size,
                       float* __restrict__ ncs_out) {
    int k = threadIdx.x;
    float ncs = cluster_size[k] * DECAY + ONE_MINUS_DECAY * g_counts[k];
    ncs_out[k] = ncs;
    __shared__ float sh[1024];
    sh[k] = ncs;
    __syncthreads();
#pragma unroll
    for (int s = 512; s > 0; s >>= 1) {
        if (k < s) sh[k] += sh[k + s];
        __syncthreads();
    }
    float n = sh[0];
    g_cs[k] = (ncs + EPSF) / (n + (float)KCODES * EPSF) * n;
}

__global__ void ema_embed(const float* __restrict__ embed_avg,
                          float* __restrict__ nea_out,
                          float* __restrict__ ne_out) {
    int idx = blockIdx.x * blockDim.x + threadIdx.x;
    if (idx >= KCODES * D) return;
    float nea = embed_avg[idx] * DECAY + ONE_MINUS_DECAY * g_embed_sum[idx];
    nea_out[idx] = nea;
    ne_out[idx] = nea / g_cs[idx >> 9];
}

// ---------------- launch ----------------
extern "C" void kernel_launch(void* const* d_in, const int* in_sizes, int n_in,
                              void* d_out, int out_size) {
    const float* x = (const float*)d_in[0];
    const float* embed = (const float*)d_in[1];
    const float* cluster_size = (const float*)d_in[2];
    const float* embed_avg = (const float*)d_in[3];

    float* out = (float*)d_out;
    float* quant = out;
    float* eind  = quant + (size_t)NROWS * D;
    float* ncs   = eind + NROWS;
    float* nea   = ncs + KCODES;
    float* ne    = nea + (size_t)KCODES * D;

    cudaFuncSetAttribute(gemm_hmma, cudaFuncAttributeMaxDynamicSharedMemorySize, SMEM_TOTAL);

    zero_scratch<<<(KCODES * D + 255) / 256, 256>>>();
    convert_x<<<NROWS * (D / 2) / 256, 256>>>(x);
    convert_b<<<KCODES * (D / 2) / 256, 256>>>(embed);
    compute_e2h<<<KCODES, 128>>>(embed);
    gemm_hmma<<<ROWTILES, 256, SMEM_TOTAL>>>();
    rescue<<<256, 256>>>(x, embed);
    gather_scatter<<<NROWS, 128>>>(x, embed, quant, eind);
    ema_cs<<<1, 1024>>>(cluster_size, ncs);
    ema_embed<<<(KCODES * D + 255) / 256, 256>>>(embed_avg, nea, ne);
}

// round 5
// speedup vs baseline: 1.6529x; 1.0463x over previous
#include <cuda_runtime.h>
#include <cuda_bf16.h>
#include <cstdint>

#define DECAY 0.99f
#define ONE_MINUS_DECAY 0.01f
#define EPSF 1e-5f
#define D 512
#define KCODES 1024
#define NROWS 65536
#define ROWTILES (NROWS / 128)   // 512
#define NTILES 128               // 8 n-chunks * 16 k-tiles
#define STAGE_BYTES 16384        // Ah/Bh each 128x32 bf16 = 8KB
#define NSTAGES 4
#define SMEM_TOTAL (NSTAGES * STAGE_BYTES)   // 64KB
#define MARGIN 0.3f
#define RG 16                    // rescue rows per block

// ---------------- device scratch ----------------
__device__ unsigned g_xhi[NROWS * D / 2];
__device__ unsigned g_bhi[KCODES * D / 2];
__device__ float g_e2h[KCODES];   // 0.5*|e|^2
__device__ float g_counts[KCODES];
__device__ float g_embed_sum[KCODES * D];
__device__ int   g_ind[NROWS];
__device__ float g_cs[KCODES];
__device__ int   g_flag[NROWS];
__device__ int   g_nflag;
__device__ int   g_cnt[KCODES];
__device__ int   g_off[KCODES];
__device__ int   g_poslist[NROWS];
__device__ int   g_rowlist[NROWS];

// ---------------- PTX helpers ----------------
__device__ __forceinline__ uint32_t smem_u32(const void* p) {
    uint32_t a;
    asm("{ .reg .u64 t; cvta.to.shared.u64 t, %1; cvt.u32.u64 %0, t; }" : "=r"(a) : "l"(p));
    return a;
}
#define CP_ASYNC16(soff, gptr) \
    asm volatile("cp.async.cg.shared.global [%0], [%1], 16;" \
                 :: "r"(soff), "l"(__cvta_generic_to_global(gptr)))
#define CP_COMMIT() asm volatile("cp.async.commit_group;" ::: "memory")
#define CP_WAIT2() asm volatile("cp.async.wait_group 2;" ::: "memory")

#define LDMX4(r, addr) \
    asm volatile("ldmatrix.sync.aligned.m8n8.x4.shared.b16 {%0,%1,%2,%3}, [%4];" \
                 : "=r"((r)[0]), "=r"((r)[1]), "=r"((r)[2]), "=r"((r)[3]) : "r"(addr))

#define MMA_BF16(c, a, b0, b1) \
    asm volatile("mma.sync.aligned.m16n8k16.row.col.f32.bf16.bf16.f32 " \
                 "{%0,%1,%2,%3}, {%4,%5,%6,%7}, {%8,%9}, {%0,%1,%2,%3};" \
                 : "+f"((c)[0]), "+f"((c)[1]), "+f"((c)[2]), "+f"((c)[3]) \
                 : "r"((a)[0]), "r"((a)[1]), "r"((a)[2]), "r"((a)[3]), "r"(b0), "r"(b1))

// ---------------- zero + prep ----------------
__global__ void zero_scratch() {
    int i = blockIdx.x * blockDim.x + threadIdx.x;
    if (i < KCODES) g_cnt[i] = 0;
    if (i == 0) g_nflag = 0;
}

__global__ void compute_e2h(const float* __restrict__ embed) {
    int k = blockIdx.x;
    int lane = threadIdx.x;
    const float4* e = (const float4*)(embed + (size_t)k * D);
    float4 v = e[lane];
    float s = v.x * v.x + v.y * v.y + v.z * v.z + v.w * v.w;
#pragma unroll
    for (int off = 16; off; off >>= 1) s += __shfl_down_sync(0xffffffffu, s, off);
    __shared__ float sh[4];
    if ((lane & 31) == 0) sh[lane >> 5] = s;
    __syncthreads();
    if (lane == 0) g_e2h[k] = 0.5f * (sh[0] + sh[1] + sh[2] + sh[3]);
}

// ---------------- bf16-hi conversion ----------------
__device__ __forceinline__ unsigned pack2(float a, float b) {
    unsigned lo = __bfloat16_as_ushort(__float2bfloat16(a));
    unsigned hi = __bfloat16_as_ushort(__float2bfloat16(b));
    return lo | (hi << 16);
}
__global__ void convert_x(const float* __restrict__ x) {
    size_t i = (size_t)blockIdx.x * blockDim.x + threadIdx.x;
    float2 v = *(const float2*)(x + i * 2);
    g_xhi[i] = pack2(v.x, v.y);
}
__global__ void convert_b(const float* __restrict__ embed) {
    size_t i = (size_t)blockIdx.x * blockDim.x + threadIdx.x;
    float2 v = *(const float2*)(embed + i * 2);
    g_bhi[i] = pack2(v.x, v.y);
}

// ---------------- HMMA GEMM (hi-only) + fused argmax ----------------
__global__ void __launch_bounds__(256, 1) gemm_hmma() {
    extern __shared__ char smem[];
    uint32_t sb = smem_u32(smem);
    const int tid = threadIdx.x;
    const int lane = tid & 31;
    const int warpM = (tid >> 5) >> 2;   // 0..1
    const int warpN = (tid >> 5) & 3;    // 0..3
    const int gid = lane >> 2, tig = lane & 3;
    const int rowTile = blockIdx.x;

    float acc[4][4][4];
    float best[8], second[8];
    int bidx[8];
#pragma unroll
    for (int s = 0; s < 8; s++) { best[s] = -3.4e38f; second[s] = -3.4e38f; bidx[s] = 0; }

    auto issue = [&](int t) {
        int nc = t >> 4, kt = t & 15;
        uint32_t st = sb + (t % NSTAGES) * STAGE_BYTES;
#pragma unroll
        for (int i = 0; i < 4; i++) {
            int idx = tid + i * 256;           // 0..1023
            int mat = idx >> 9;                // 0 Ah, 1 Bh
            int id2 = idx & 511;
            int row = id2 >> 2, c = id2 & 3;
            uint32_t soff = st + mat * 8192 + row * 64 + ((c ^ ((row >> 1) & 3)) << 4);
            size_t goff = (mat == 0)
                ? ((size_t)(rowTile * 128 + row) * D + kt * 32 + c * 8) >> 1
                : ((size_t)(nc * 128 + row) * D + kt * 32 + c * 8) >> 1;
            const unsigned* gp = (mat == 0) ? g_xhi + goff : g_bhi + goff;
            CP_ASYNC16(soff, gp);
        }
        CP_COMMIT();
    };

    issue(0); issue(1); issue(2);

    for (int t = 0; t < NTILES; t++) {
        CP_WAIT2();
        __syncthreads();
        if (t + 3 < NTILES) issue(t + 3); else CP_COMMIT();

        if ((t & 15) == 0) {
#pragma unroll
            for (int m = 0; m < 4; m++)
#pragma unroll
                for (int n = 0; n < 4; n++)
#pragma unroll
                    for (int j = 0; j < 4; j++) acc[m][n][j] = 0.0f;
        }

        uint32_t st = sb + (t % NSTAGES) * STAGE_BYTES;
#pragma unroll
        for (int ks = 0; ks < 2; ks++) {
            uint32_t ah[4][4], bh[2][4];
#pragma unroll
            for (int m = 0; m < 4; m++) {
                int r = warpM * 64 + m * 16 + (lane & 15);
                int kc = ks * 2 + (lane >> 4);
                uint32_t a = st + r * 64 + ((kc ^ ((r >> 1) & 3)) << 4);
                LDMX4(ah[m], a);
            }
#pragma unroll
            for (int p = 0; p < 2; p++) {
                int grp = lane >> 3;
                int nt = p * 2 + (grp >> 1);
                int kc = ks * 2 + (grp & 1);
                int r = warpN * 32 + nt * 8 + (lane & 7);
                uint32_t a = st + 8192 + r * 64 + ((kc ^ ((r >> 1) & 3)) << 4);
                LDMX4(bh[p], a);
            }
#pragma unroll
            for (int m = 0; m < 4; m++)
#pragma unroll
                for (int n = 0; n < 4; n++) {
                    uint32_t b0h = bh[n >> 1][(n & 1) * 2], b1h = bh[n >> 1][(n & 1) * 2 + 1];
                    MMA_BF16(acc[m][n], ah[m], b0h, b1h);
                }
        }

        if ((t & 15) == 15) {
            int nc = t >> 4;
#pragma unroll
            for (int n = 0; n < 4; n++) {
                int col0 = nc * 128 + warpN * 32 + n * 8 + tig * 2;
                float e0 = __ldg(&g_e2h[col0]);
                float e1 = __ldg(&g_e2h[col0 + 1]);
#pragma unroll
                for (int m = 0; m < 4; m++)
#pragma unroll
                    for (int h = 0; h < 2; h++) {
                        int slot = m * 2 + h;
                        float s0 = acc[m][n][h * 2 + 0] - e0;
                        float s1 = acc[m][n][h * 2 + 1] - e1;
                        if (s0 > best[slot]) { second[slot] = best[slot]; best[slot] = s0; bidx[slot] = col0; }
                        else if (s0 > second[slot]) second[slot] = s0;
                        if (s1 > best[slot]) { second[slot] = best[slot]; best[slot] = s1; bidx[slot] = col0 + 1; }
                        else if (s1 > second[slot]) second[slot] = s1;
                    }
            }
        }
    }

    __syncthreads();
    float* mb = (float*)smem;          // [128][4]
    float* ms = mb + 512;
    int*   mi = (int*)(ms + 512);
#pragma unroll
    for (int slot = 0; slot < 8; slot++) {
        float b = best[slot], s = second[slot];
        int i = bidx[slot];
#pragma unroll
        for (int off = 1; off <= 2; off <<= 1) {
            float ob = __shfl_xor_sync(0xffffffffu, b, off);
            float os = __shfl_xor_sync(0xffffffffu, s, off);
            int   oi = __shfl_xor_sync(0xffffffffu, i, off);
            if (ob > b || (ob == b && oi < i)) { s = fmaxf(os, b); b = ob; i = oi; }
            else s = fmaxf(s, ob);
        }
        if (tig == 0) {
            int row = warpM * 64 + (slot >> 1) * 16 + gid + (slot & 1) * 8;
            mb[row * 4 + warpN] = b; ms[row * 4 + warpN] = s; mi[row * 4 + warpN] = i;
        }
    }
    __syncthreads();
    if (tid < 128) {
        int row = tid;
        float b = mb[row * 4], s = ms[row * 4];
        int i = mi[row * 4];
#pragma unroll
        for (int w = 1; w < 4; w++) {
            float ob = mb[row * 4 + w], os = ms[row * 4 + w];
            int oi = mi[row * 4 + w];
            if (ob > b || (ob == b && oi < i)) { s = fmaxf(os, b); b = ob; i = oi; }
            else s = fmaxf(s, ob);
        }
        int grow = rowTile * 128 + row;
        g_ind[grow] = i;
        if (b - s < MARGIN) {
            int p = atomicAdd(&g_nflag, 1);
            g_flag[p] = grow;
        }
    }
}

// ---------------- exact fp32 rescue: 16 rows/block, warp per code ----------------
__global__ void __launch_bounds__(512) rescue(const float* __restrict__ x,
                                              const float* __restrict__ embed) {
    __shared__ float xs[RG][512];        // 32KB
    __shared__ float mbv[16][RG];
    __shared__ int   mbi[16][RG];
    int tid = threadIdx.x;
    int w = tid >> 5, lane = tid & 31;
    int nf = g_nflag;
    for (int base = blockIdx.x * RG; base < nf; base += gridDim.x * RG) {
        int cnt = min(RG, nf - base);
        __syncthreads();
        for (int i = tid; i < cnt * 512; i += 512) {
            int r = i >> 9, j = i & 511;
            xs[r][j] = x[(size_t)g_flag[base + r] * 512 + j];
        }
        __syncthreads();
        float bb = -3.4e38f;
        int bi = 0;
        for (int c = w; c < KCODES; c += 16) {
            float acc[RG];
#pragma unroll
            for (int r = 0; r < RG; r++) acc[r] = 0.0f;
            const float4* ep = (const float4*)(embed + (size_t)c * 512);
#pragma unroll
            for (int jj = 0; jj < 4; jj++) {
                float4 e = __ldg(&ep[lane + jj * 32]);
                int j = (lane + jj * 32) * 4;
#pragma unroll
                for (int r = 0; r < RG; r++) {
                    float4 xv = *(float4*)&xs[r][j];
                    acc[r] = fmaf(xv.x, e.x, fmaf(xv.y, e.y,
                              fmaf(xv.z, e.z, fmaf(xv.w, e.w, acc[r]))));
                }
            }
#pragma unroll
            for (int r = 0; r < RG; r++) {
#pragma unroll
                for (int off = 16; off; off >>= 1)
                    acc[r] += __shfl_xor_sync(0xffffffffu, acc[r], off);
            }
            if (lane < cnt) {
                float s = acc[lane] - g_e2h[c];
                if (s > bb || (s == bb && c < bi)) { bb = s; bi = c; }
            }
        }
        if (lane < RG) { mbv[w][lane] = bb; mbi[w][lane] = bi; }
        __syncthreads();
        if (tid < cnt) {
            float b = mbv[0][tid]; int i = mbi[0][tid];
#pragma unroll
            for (int ww = 1; ww < 16; ww++) {
                float ob = mbv[ww][tid]; int oi = mbi[ww][tid];
                if (ob > b || (ob == b && oi < i)) { b = ob; i = oi; }
            }
            g_ind[g_flag[base + tid]] = i;
        }
    }
}

// ---------------- quant gather + per-code counting ----------------
__global__ void quant_gather(const float* __restrict__ embed,
                             float* __restrict__ quant,
                             float* __restrict__ eind) {
    int row = blockIdx.x;
    int k = g_ind[row];
    if (threadIdx.x == 0) {
        g_poslist[row] = atomicAdd(&g_cnt[k], 1);
        eind[row] = (float)k;
    }
    int c = threadIdx.x;
    float4 ev = *(const float4*)(embed + (size_t)k * D + c * 4);
    *(float4*)(quant + (size_t)row * D + c * 4) = ev;
}

__global__ void scan_counts() {
    int k = threadIdx.x;
    __shared__ int s[1024];
    int my = g_cnt[k];
    s[k] = my;
    __syncthreads();
#pragma unroll
    for (int off = 1; off < 1024; off <<= 1) {
        int v = (k >= off) ? s[k - off] : 0;
        __syncthreads();
        s[k] += v;
        __syncthreads();
    }
    g_off[k] = s[k] - my;
    g_counts[k] = (float)my;
}

__global__ void fill_rowlist() {
    int row = blockIdx.x * blockDim.x + threadIdx.x;
    int k = g_ind[row];
    g_rowlist[g_off[k] + g_poslist[row]] = row;
}

__global__ void sum_by_code(const float* __restrict__ x) {
    int c = blockIdx.x;
    int n = g_cnt[c], off = g_off[c];
    int col = threadIdx.x * 4;
    float4 acc = {0.f, 0.f, 0.f, 0.f};
    for (int i = 0; i < n; i++) {
        int row = __ldg(&g_rowlist[off + i]);
        float4 v = *(const float4*)(x + (size_t)row * D + col);
        acc.x += v.x; acc.y += v.y; acc.z += v.z; acc.w += v.w;
    }
    *(float4*)(g_embed_sum + (size_t)c * D + col) = acc;
}

// ---------------- EMA epilogues ----------------
__global__ void ema_cs(const float* __restrict__ cluster_size,
                       float* __restrict__ ncs_out) {
    int k = threadIdx.x;
    float ncs = cluster_size[k] * DECAY + ONE_MINUS_DECAY * g_counts[k];
    ncs_out[k] = ncs;
    __shared__ float sh[1024];
    sh[k] = ncs;
    __syncthreads();
#pragma unroll
    for (int s = 512; s > 0; s >>= 1) {
        if (k < s) sh[k] += sh[k + s];
        __syncthreads();
    }
    float n = sh[0];
    g_cs[k] = (ncs + EPSF) / (n + (float)KCODES * EPSF) * n;
}

__global__ void ema_embed(const float* __restrict__ embed_avg,
                          float* __restrict__ nea_out,
                          float* __restrict__ ne_out) {
    int idx = blockIdx.x * blockDim.x + threadIdx.x;
    if (idx >= KCODES * D) return;
    float nea = embed_avg[idx] * DECAY + ONE_MINUS_DECAY * g_embed_sum[idx];
    nea_out[idx] = nea;
    ne_out[idx] = nea / g_cs[idx >> 9];
}

// ---------------- launch ----------------
extern "C" void kernel_launch(void* const* d_in, const int* in_sizes, int n_in,
                              void* d_out, int out_size) {
    const float* x = (const float*)d_in[0];
    const float* embed = (const float*)d_in[1];
    const float* cluster_size = (const float*)d_in[2];
    const float* embed_avg = (const float*)d_in[3];

    float* out = (float*)d_out;
    float* quant = out;
    float* eind  = quant + (size_t)NROWS * D;
    float* ncs   = eind + NROWS;
    float* nea   = ncs + KCODES;
    float* ne    = nea + (size_t)KCODES * D;

    cudaFuncSetAttribute(gemm_hmma, cudaFuncAttributeMaxDynamicSharedMemorySize, SMEM_TOTAL);

    zero_scratch<<<(KCODES + 255) / 256, 256>>>();
    convert_x<<<NROWS * (D / 2) / 256, 256>>>(x);
    convert_b<<<KCODES * (D / 2) / 256, 256>>>(embed);
    compute_e2h<<<KCODES, 128>>>(embed);
    gemm_hmma<<<ROWTILES, 256, SMEM_TOTAL>>>();
    rescue<<<166, 512>>>(x, embed);
    quant_gather<<<NROWS, 128>>>(embed, quant, eind);
    scan_counts<<<1, 1024>>>();
    fill_rowlist<<<NROWS / 256, 256>>>();
    sum_by_code<<<KCODES, 128>>>(x);
    ema_cs<<<1, 1024>>>(cluster_size, ncs);
    ema_embed<<<(KCODES * D + 255) / 256, 256>>>(embed_avg, nea, ne);
}

// round 6
// speedup vs baseline: 1.6946x; 1.0252x over previous
#include <cuda_runtime.h>
#include <cuda_bf16.h>
#include <cstdint>

#define DECAY 0.99f
#define ONE_MINUS_DECAY 0.01f
#define EPSF 1e-5f
#define D 512
#define KCODES 1024
#define NROWS 65536
#define ROWTILES (NROWS / 128)   // 512
#define NTILES 128               // 8 n-chunks * 16 k-tiles
#define STAGE_BYTES 16384        // A/B each 128x32 bf16 = 8KB
#define NSTAGES 5
#define SMEM_TOTAL (NSTAGES * STAGE_BYTES)   // 80KB
#define MARGIN 0.3f
#define RG 16                    // rescue rows per block

// ---------------- device scratch ----------------
__device__ unsigned g_xhi[NROWS * D / 2];
__device__ unsigned g_bhi[KCODES * D / 2];
__device__ float g_e2h[KCODES];   // 0.5*|e|^2
__device__ float g_counts[KCODES];
__device__ float g_embed_sum[KCODES * D];
__device__ int   g_ind[NROWS];
__device__ float g_cs[KCODES];
__device__ int   g_flag[NROWS];
__device__ int   g_nflag;
__device__ int   g_cnt[KCODES];
__device__ int   g_off[KCODES];
__device__ int   g_poslist[NROWS];
__device__ int   g_rowlist[NROWS];

// ---------------- PTX helpers ----------------
__device__ __forceinline__ uint32_t smem_u32(const void* p) {
    uint32_t a;
    asm("{ .reg .u64 t; cvta.to.shared.u64 t, %1; cvt.u32.u64 %0, t; }" : "=r"(a) : "l"(p));
    return a;
}
#define CP_ASYNC16(soff, gptr) \
    asm volatile("cp.async.cg.shared.global [%0], [%1], 16;" \
                 :: "r"(soff), "l"(__cvta_generic_to_global(gptr)))
#define CP_COMMIT() asm volatile("cp.async.commit_group;" ::: "memory")
#define CP_WAIT3() asm volatile("cp.async.wait_group 3;" ::: "memory")

#define LDMX4(r, addr) \
    asm volatile("ldmatrix.sync.aligned.m8n8.x4.shared.b16 {%0,%1,%2,%3}, [%4];" \
                 : "=r"((r)[0]), "=r"((r)[1]), "=r"((r)[2]), "=r"((r)[3]) : "r"(addr))

#define MMA_BF16(c, a, b0, b1) \
    asm volatile("mma.sync.aligned.m16n8k16.row.col.f32.bf16.bf16.f32 " \
                 "{%0,%1,%2,%3}, {%4,%5,%6,%7}, {%8,%9}, {%0,%1,%2,%3};" \
                 : "+f"((c)[0]), "+f"((c)[1]), "+f"((c)[2]), "+f"((c)[3]) \
                 : "r"((a)[0]), "r"((a)[1]), "r"((a)[2]), "r"((a)[3]), "r"(b0), "r"(b1))

// ---------------- zero + prep ----------------
__global__ void zero_scratch() {
    int i = blockIdx.x * blockDim.x + threadIdx.x;
    if (i < KCODES) g_cnt[i] = 0;
    if (i == 0) g_nflag = 0;
}

__global__ void compute_e2h(const float* __restrict__ embed) {
    int k = blockIdx.x;
    int lane = threadIdx.x;
    const float4* e = (const float4*)(embed + (size_t)k * D);
    float4 v = e[lane];
    float s = v.x * v.x + v.y * v.y + v.z * v.z + v.w * v.w;
#pragma unroll
    for (int off = 16; off; off >>= 1) s += __shfl_down_sync(0xffffffffu, s, off);
    __shared__ float sh[4];
    if ((lane & 31) == 0) sh[lane >> 5] = s;
    __syncthreads();
    if (lane == 0) g_e2h[k] = 0.5f * (sh[0] + sh[1] + sh[2] + sh[3]);
}

// ---------------- bf16-hi conversion ----------------
__device__ __forceinline__ unsigned pack2(float a, float b) {
    unsigned lo = __bfloat16_as_ushort(__float2bfloat16(a));
    unsigned hi = __bfloat16_as_ushort(__float2bfloat16(b));
    return lo | (hi << 16);
}
__global__ void convert_x(const float* __restrict__ x) {
    size_t i = (size_t)blockIdx.x * blockDim.x + threadIdx.x;
    float2 v = *(const float2*)(x + i * 2);
    g_xhi[i] = pack2(v.x, v.y);
}
__global__ void convert_b(const float* __restrict__ embed) {
    size_t i = (size_t)blockIdx.x * blockDim.x + threadIdx.x;
    float2 v = *(const float2*)(embed + i * 2);
    g_bhi[i] = pack2(v.x, v.y);
}

// ---------------- HMMA GEMM (hi-only) + fused argmax ----------------
// 512 threads = 16 warps (4M x 4N), warp tile 32x32, block tile 128x128, BK=32.
__global__ void __launch_bounds__(512, 1) gemm_hmma() {
    extern __shared__ char smem[];
    uint32_t sb = smem_u32(smem);
    const int tid = threadIdx.x;
    const int lane = tid & 31;
    const int warpM = (tid >> 5) >> 2;   // 0..3
    const int warpN = (tid >> 5) & 3;    // 0..3
    const int gid = lane >> 2, tig = lane & 3;
    const int rowTile = blockIdx.x;

    float acc[2][4][4];
    float best[4], second[4];
    int bidx[4];
#pragma unroll
    for (int s = 0; s < 4; s++) { best[s] = -3.4e38f; second[s] = -3.4e38f; bidx[s] = 0; }

    auto issue = [&](int t) {
        int nc = t >> 4, kt = t & 15;
        uint32_t st = sb + (t % NSTAGES) * STAGE_BYTES;
#pragma unroll
        for (int i = 0; i < 2; i++) {
            int idx = tid + i * 512;           // 0..1023
            int mat = idx >> 9;                // 0 A, 1 B
            int id2 = idx & 511;
            int row = id2 >> 2, c = id2 & 3;
            uint32_t soff = st + mat * 8192 + row * 64 + ((c ^ ((row >> 1) & 3)) << 4);
            size_t goff = (mat == 0)
                ? ((size_t)(rowTile * 128 + row) * D + kt * 32 + c * 8) >> 1
                : ((size_t)(nc * 128 + row) * D + kt * 32 + c * 8) >> 1;
            const unsigned* gp = (mat == 0) ? g_xhi + goff : g_bhi + goff;
            CP_ASYNC16(soff, gp);
        }
        CP_COMMIT();
    };

    issue(0); issue(1); issue(2); issue(3);

    for (int t = 0; t < NTILES; t++) {
        CP_WAIT3();
        __syncthreads();
        if (t + 4 < NTILES) issue(t + 4); else CP_COMMIT();

        if ((t & 15) == 0) {
#pragma unroll
            for (int m = 0; m < 2; m++)
#pragma unroll
                for (int n = 0; n < 4; n++)
#pragma unroll
                    for (int j = 0; j < 4; j++) acc[m][n][j] = 0.0f;
        }

        uint32_t st = sb + (t % NSTAGES) * STAGE_BYTES;
#pragma unroll
        for (int ks = 0; ks < 2; ks++) {
            uint32_t ah[2][4], bh[2][4];
#pragma unroll
            for (int m = 0; m < 2; m++) {
                int r = warpM * 32 + m * 16 + (lane & 15);
                int kc = ks * 2 + (lane >> 4);
                uint32_t a = st + r * 64 + ((kc ^ ((r >> 1) & 3)) << 4);
                LDMX4(ah[m], a);
            }
#pragma unroll
            for (int p = 0; p < 2; p++) {
                int grp = lane >> 3;
                int nt = p * 2 + (grp >> 1);
                int kc = ks * 2 + (grp & 1);
                int r = warpN * 32 + nt * 8 + (lane & 7);
                uint32_t a = st + 8192 + r * 64 + ((kc ^ ((r >> 1) & 3)) << 4);
                LDMX4(bh[p], a);
            }
#pragma unroll
            for (int m = 0; m < 2; m++)
#pragma unroll
                for (int n = 0; n < 4; n++) {
                    uint32_t b0h = bh[n >> 1][(n & 1) * 2], b1h = bh[n >> 1][(n & 1) * 2 + 1];
                    MMA_BF16(acc[m][n], ah[m], b0h, b1h);
                }
        }

        if ((t & 15) == 15) {
            int nc = t >> 4;
#pragma unroll
            for (int n = 0; n < 4; n++) {
                int col0 = nc * 128 + warpN * 32 + n * 8 + tig * 2;
                float e0 = __ldg(&g_e2h[col0]);
                float e1 = __ldg(&g_e2h[col0 + 1]);
#pragma unroll
                for (int m = 0; m < 2; m++)
#pragma unroll
                    for (int h = 0; h < 2; h++) {
                        int slot = m * 2 + h;
                        float s0 = acc[m][n][h * 2 + 0] - e0;
                        float s1 = acc[m][n][h * 2 + 1] - e1;
                        if (s0 > best[slot]) { second[slot] = best[slot]; best[slot] = s0; bidx[slot] = col0; }
                        else if (s0 > second[slot]) second[slot] = s0;
                        if (s1 > best[slot]) { second[slot] = best[slot]; best[slot] = s1; bidx[slot] = col0 + 1; }
                        else if (s1 > second[slot]) second[slot] = s1;
                    }
            }
        }
    }

    __syncthreads();
    float* mb = (float*)smem;          // [128][4]
    float* ms = mb + 512;
    int*   mi = (int*)(ms + 512);
#pragma unroll
    for (int slot = 0; slot < 4; slot++) {
        float b = best[slot], s = second[slot];
        int i = bidx[slot];
#pragma unroll
        for (int off = 1; off <= 2; off <<= 1) {
            float ob = __shfl_xor_sync(0xffffffffu, b, off);
            float os = __shfl_xor_sync(0xffffffffu, s, off);
            int   oi = __shfl_xor_sync(0xffffffffu, i, off);
            if (ob > b || (ob == b && oi < i)) { s = fmaxf(os, b); b = ob; i = oi; }
            else s = fmaxf(s, ob);
        }
        if (tig == 0) {
            int row = warpM * 32 + (slot >> 1) * 16 + gid + (slot & 1) * 8;
            mb[row * 4 + warpN] = b; ms[row * 4 + warpN] = s; mi[row * 4 + warpN] = i;
        }
    }
    __syncthreads();
    if (tid < 128) {
        int row = tid;
        float b = mb[row * 4], s = ms[row * 4];
        int i = mi[row * 4];
#pragma unroll
        for (int w = 1; w < 4; w++) {
            float ob = mb[row * 4 + w], os = ms[row * 4 + w];
            int oi = mi[row * 4 + w];
            if (ob > b || (ob == b && oi < i)) { s = fmaxf(os, b); b = ob; i = oi; }
            else s = fmaxf(s, ob);
        }
        int grow = rowTile * 128 + row;
        g_ind[grow] = i;
        if (b - s < MARGIN) {
            int p = atomicAdd(&g_nflag, 1);
            g_flag[p] = grow;
        }
    }
}

// ---------------- exact fp32 rescue: 16 rows/block, warp per code ----------------
__global__ void __launch_bounds__(512) rescue(const float* __restrict__ x,
                                              const float* __restrict__ embed) {
    __shared__ float xs[RG][512];        // 32KB
    __shared__ float mbv[16][RG];
    __shared__ int   mbi[16][RG];
    int tid = threadIdx.x;
    int w = tid >> 5, lane = tid & 31;
    int nf = g_nflag;
    for (int base = blockIdx.x * RG; base < nf; base += gridDim.x * RG) {
        int cnt = min(RG, nf - base);
        __syncthreads();
        for (int i = tid; i < cnt * 512; i += 512) {
            int r = i >> 9, j = i & 511;
            xs[r][j] = x[(size_t)g_flag[base + r] * 512 + j];
        }
        __syncthreads();
        float bb = -3.4e38f;
        int bi = 0;
        for (int c = w; c < KCODES; c += 16) {
            float acc[RG];
#pragma unroll
            for (int r = 0; r < RG; r++) acc[r] = 0.0f;
            const float4* ep = (const float4*)(embed + (size_t)c * 512);
#pragma unroll
            for (int jj = 0; jj < 4; jj++) {
                float4 e = __ldg(&ep[lane + jj * 32]);
                int j = (lane + jj * 32) * 4;
#pragma unroll
                for (int r = 0; r < RG; r++) {
                    float4 xv = *(float4*)&xs[r][j];
                    acc[r] = fmaf(xv.x, e.x, fmaf(xv.y, e.y,
                              fmaf(xv.z, e.z, fmaf(xv.w, e.w, acc[r]))));
                }
            }
#pragma unroll
            for (int r = 0; r < RG; r++) {
#pragma unroll
                for (int off = 16; off; off >>= 1)
                    acc[r] += __shfl_xor_sync(0xffffffffu, acc[r], off);
            }
            if (lane < cnt) {
                float s = acc[lane] - g_e2h[c];
                if (s > bb || (s == bb && c < bi)) { bb = s; bi = c; }
            }
        }
        if (lane < RG) { mbv[w][lane] = bb; mbi[w][lane] = bi; }
        __syncthreads();
        if (tid < cnt) {
            float b = mbv[0][tid]; int i = mbi[0][tid];
#pragma unroll
            for (int ww = 1; ww < 16; ww++) {
                float ob = mbv[ww][tid]; int oi = mbi[ww][tid];
                if (ob > b || (ob == b && oi < i)) { b = ob; i = oi; }
            }
            g_ind[g_flag[base + tid]] = i;
        }
    }
}

// ---------------- quant gather + per-code counting ----------------
__global__ void quant_gather(const float* __restrict__ embed,
                             float* __restrict__ quant,
                             float* __restrict__ eind) {
    int row = blockIdx.x;
    int k = g_ind[row];
    if (threadIdx.x == 0) {
        g_poslist[row] = atomicAdd(&g_cnt[k], 1);
        eind[row] = (float)k;
    }
    int c = threadIdx.x;
    float4 ev = *(const float4*)(embed + (size_t)k * D + c * 4);
    *(float4*)(quant + (size_t)row * D + c * 4) = ev;
}

__global__ void scan_counts() {
    int k = threadIdx.x;
    __shared__ int s[1024];
    int my = g_cnt[k];
    s[k] = my;
    __syncthreads();
#pragma unroll
    for (int off = 1; off < 1024; off <<= 1) {
        int v = (k >= off) ? s[k - off] : 0;
        __syncthreads();
        s[k] += v;
        __syncthreads();
    }
    g_off[k] = s[k] - my;
    g_counts[k] = (float)my;
}

__global__ void fill_rowlist() {
    int row = blockIdx.x * blockDim.x + threadIdx.x;
    int k = g_ind[row];
    g_rowlist[g_off[k] + g_poslist[row]] = row;
}

__global__ void sum_by_code(const float* __restrict__ x) {
    int c = blockIdx.x;
    int n = g_cnt[c], off = g_off[c];
    int col = threadIdx.x * 4;
    float4 acc = {0.f, 0.f, 0.f, 0.f};
    for (int i = 0; i < n; i++) {
        int row = __ldg(&g_rowlist[off + i]);
        float4 v = *(const float4*)(x + (size_t)row * D + col);
        acc.x += v.x; acc.y += v.y; acc.z += v.z; acc.w += v.w;
    }
    *(float4*)(g_embed_sum + (size_t)c * D + col) = acc;
}

// ---------------- EMA epilogues ----------------
__global__ void ema_cs(const float* __restrict__ cluster_size,
                       float* __restrict__ ncs_out) {
    int k = threadIdx.x;
    float ncs = cluster_size[k] * DECAY + ONE_MINUS_DECAY * g_counts[k];
    ncs_out[k] = ncs;
    __shared__ float sh[1024];
    sh[k] = ncs;
    __syncthreads();
#pragma unroll
    for (int s = 512; s > 0; s >>= 1) {
        if (k < s) sh[k] += sh[k + s];
        __syncthreads();
    }
    float n = sh[0];
    g_cs[k] = (ncs + EPSF) / (n + (float)KCODES * EPSF) * n;
}

__global__ void ema_embed(const float* __restrict__ embed_avg,
                          float* __restrict__ nea_out,
                          float* __restrict__ ne_out) {
    int idx = blockIdx.x * blockDim.x + threadIdx.x;
    if (idx >= KCODES * D) return;
    float nea = embed_avg[idx] * DECAY + ONE_MINUS_DECAY * g_embed_sum[idx];
    nea_out[idx] = nea;
    ne_out[idx] = nea / g_cs[idx >> 9];
}

// ---------------- launch ----------------
extern "C" void kernel_launch(void* const* d_in, const int* in_sizes, int n_in,
                              void* d_out, int out_size) {
    const float* x = (const float*)d_in[0];
    const float* embed = (const float*)d_in[1];
    const float* cluster_size = (const float*)d_in[2];
    const float* embed_avg = (const float*)d_in[3];

    float* out = (float*)d_out;
    float* quant = out;
    float* eind  = quant + (size_t)NROWS * D;
    float* ncs   = eind + NROWS;
    float* nea   = ncs + KCODES;
    float* ne    = nea + (size_t)KCODES * D;

    cudaFuncSetAttribute(gemm_hmma, cudaFuncAttributeMaxDynamicSharedMemorySize, SMEM_TOTAL);

    zero_scratch<<<(KCODES + 255) / 256, 256>>>();
    convert_x<<<NROWS * (D / 2) / 256, 256>>>(x);
    convert_b<<<KCODES * (D / 2) / 256, 256>>>(embed);
    compute_e2h<<<KCODES, 128>>>(embed);
    gemm_hmma<<<ROWTILES, 512, SMEM_TOTAL>>>();
    rescue<<<166, 512>>>(x, embed);
    quant_gather<<<NROWS, 128>>>(embed, quant, eind);
    scan_counts<<<1, 1024>>>();
    fill_rowlist<<<NROWS / 256, 256>>>();
    sum_by_code<<<KCODES, 128>>>(x);
    ema_cs<<<1, 1024>>>(cluster_size, ncs);
    ema_embed<<<(KCODES * D + 255) / 256, 256>>>(embed_avg, nea, ne);
}

// round 7
// speedup vs baseline: 1.7638x; 1.0408x over previous
#include <cuda_runtime.h>
#include <cuda_bf16.h>
#include <cstdint>

#define DECAY 0.99f
#define ONE_MINUS_DECAY 0.01f
#define EPSF 1e-5f
#define D 512
#define KCODES 1024
#define NROWS 65536
#define ROWTILES (NROWS / 128)   // 512
#define NTILES 64                // 8 n-chunks * 8 k-tiles (BK=64)
#define STAGE_BYTES 32768        // A/B each 128x64 bf16 = 16KB
#define NSTAGES 4
#define SMEM_TOTAL (NSTAGES * STAGE_BYTES)   // 128KB
#define MARGIN 0.3f
#define RG 16                    // rescue rows per block

// ---------------- device scratch ----------------
__device__ unsigned g_xhi[NROWS * D / 2];
__device__ unsigned g_bhi[KCODES * D / 2];
__device__ float g_e2h[KCODES];   // 0.5*|e|^2
__device__ float g_counts[KCODES];
__device__ float g_embed_sum[KCODES * D];
__device__ int   g_ind[NROWS];
__device__ float g_cs[KCODES];
__device__ int   g_flag[NROWS];
__device__ int   g_nflag;
__device__ int   g_cnt[KCODES];
__device__ int   g_off[KCODES];
__device__ int   g_poslist[NROWS];
__device__ int   g_rowlist[NROWS];

// ---------------- PTX helpers ----------------
__device__ __forceinline__ uint32_t smem_u32(const void* p) {
    uint32_t a;
    asm("{ .reg .u64 t; cvta.to.shared.u64 t, %1; cvt.u32.u64 %0, t; }" : "=r"(a) : "l"(p));
    return a;
}
#define CP_ASYNC16(soff, gptr) \
    asm volatile("cp.async.cg.shared.global [%0], [%1], 16;" \
                 :: "r"(soff), "l"(__cvta_generic_to_global(gptr)))
#define CP_COMMIT() asm volatile("cp.async.commit_group;" ::: "memory")
#define CP_WAIT2() asm volatile("cp.async.wait_group 2;" ::: "memory")

#define LDMX4(r, addr) \
    asm volatile("ldmatrix.sync.aligned.m8n8.x4.shared.b16 {%0,%1,%2,%3}, [%4];" \
                 : "=r"((r)[0]), "=r"((r)[1]), "=r"((r)[2]), "=r"((r)[3]) : "r"(addr))

#define MMA_BF16(c, a, b0, b1) \
    asm volatile("mma.sync.aligned.m16n8k16.row.col.f32.bf16.bf16.f32 " \
                 "{%0,%1,%2,%3}, {%4,%5,%6,%7}, {%8,%9}, {%0,%1,%2,%3};" \
                 : "+f"((c)[0]), "+f"((c)[1]), "+f"((c)[2]), "+f"((c)[3]) \
                 : "r"((a)[0]), "r"((a)[1]), "r"((a)[2]), "r"((a)[3]), "r"(b0), "r"(b1))

// ---------------- e2h + zero fold (launch #1) ----------------
__global__ void compute_e2h(const float* __restrict__ embed) {
    int k = blockIdx.x;
    int lane = threadIdx.x;
    if (lane == 33) g_cnt[k] = 0;            // fold CSR-count zeroing
    if (k == 0 && lane == 34) g_nflag = 0;
    const float4* e = (const float4*)(embed + (size_t)k * D);
    float4 v = e[lane & 127];
    float s = v.x * v.x + v.y * v.y + v.z * v.z + v.w * v.w;
#pragma unroll
    for (int off = 16; off; off >>= 1) s += __shfl_down_sync(0xffffffffu, s, off);
    __shared__ float sh[4];
    if ((lane & 31) == 0) sh[lane >> 5] = s;
    __syncthreads();
    if (lane == 0) g_e2h[k] = 0.5f * (sh[0] + sh[1] + sh[2] + sh[3]);
}

// ---------------- bf16-hi conversion ----------------
__device__ __forceinline__ unsigned pack2(float a, float b) {
    unsigned lo = __bfloat16_as_ushort(__float2bfloat16(a));
    unsigned hi = __bfloat16_as_ushort(__float2bfloat16(b));
    return lo | (hi << 16);
}
__global__ void convert_x(const float* __restrict__ x) {
    size_t i = (size_t)blockIdx.x * blockDim.x + threadIdx.x;
    float2 v = *(const float2*)(x + i * 2);
    g_xhi[i] = pack2(v.x, v.y);
}
__global__ void convert_b(const float* __restrict__ embed) {
    size_t i = (size_t)blockIdx.x * blockDim.x + threadIdx.x;
    float2 v = *(const float2*)(embed + i * 2);
    g_bhi[i] = pack2(v.x, v.y);
}

// ---------------- HMMA GEMM (hi-only, BK=64) + fused argmax ----------------
// 512 threads = 16 warps (4M x 4N), warp tile 32x32, block tile 128x128, BK=64.
// SMEM rows are 128B -> canonical conflict-free SW128 swizzle.
__global__ void __launch_bounds__(512, 1) gemm_hmma() {
    extern __shared__ char smem[];
    uint32_t sb = smem_u32(smem);
    const int tid = threadIdx.x;
    const int lane = tid & 31;
    const int warpM = (tid >> 5) >> 2;   // 0..3
    const int warpN = (tid >> 5) & 3;    // 0..3
    const int gid = lane >> 2, tig = lane & 3;
    const int rowTile = blockIdx.x;

    float acc[2][4][4];
    float best[4], second[4];
    int bidx[4];
#pragma unroll
    for (int s = 0; s < 4; s++) { best[s] = -3.4e38f; second[s] = -3.4e38f; bidx[s] = 0; }

    auto issue = [&](int t) {
        int nc = t >> 3, kt = t & 7;
        uint32_t st = sb + (t & (NSTAGES - 1)) * STAGE_BYTES;
#pragma unroll
        for (int i = 0; i < 4; i++) {
            int idx = tid + i * 512;           // 0..2047
            int mat = idx >> 10;               // 0 A, 1 B
            int id2 = idx & 1023;
            int row = id2 >> 3, g = id2 & 7;
            uint32_t soff = st + mat * 16384 + row * 128 + ((g ^ (row & 7)) << 4);
            size_t goff = (mat == 0)
                ? ((size_t)(rowTile * 128 + row) * D + kt * 64 + g * 8) >> 1
                : ((size_t)(nc * 128 + row) * D + kt * 64 + g * 8) >> 1;
            const unsigned* gp = (mat == 0) ? g_xhi + goff : g_bhi + goff;
            CP_ASYNC16(soff, gp);
        }
        CP_COMMIT();
    };

    issue(0); issue(1); issue(2);

    for (int t = 0; t < NTILES; t++) {
        CP_WAIT2();
        __syncthreads();
        if (t + 3 < NTILES) issue(t + 3); else CP_COMMIT();

        if ((t & 7) == 0) {
#pragma unroll
            for (int m = 0; m < 2; m++)
#pragma unroll
                for (int n = 0; n < 4; n++)
#pragma unroll
                    for (int j = 0; j < 4; j++) acc[m][n][j] = 0.0f;
        }

        uint32_t st = sb + (t & (NSTAGES - 1)) * STAGE_BYTES;
#pragma unroll
        for (int ks = 0; ks < 4; ks++) {
            uint32_t ah[2][4], bh[2][4];
#pragma unroll
            for (int m = 0; m < 2; m++) {
                int r = warpM * 32 + m * 16 + (lane & 15);
                int kc = ks * 2 + (lane >> 4);
                uint32_t a = st + r * 128 + ((kc ^ (r & 7)) << 4);
                LDMX4(ah[m], a);
            }
#pragma unroll
            for (int p = 0; p < 2; p++) {
                int grp = lane >> 3;
                int nt = p * 2 + (grp >> 1);
                int kc = ks * 2 + (grp & 1);
                int r = warpN * 32 + nt * 8 + (lane & 7);
                uint32_t a = st + 16384 + r * 128 + ((kc ^ (r & 7)) << 4);
                LDMX4(bh[p], a);
            }
#pragma unroll
            for (int m = 0; m < 2; m++)
#pragma unroll
                for (int n = 0; n < 4; n++) {
                    uint32_t b0h = bh[n >> 1][(n & 1) * 2], b1h = bh[n >> 1][(n & 1) * 2 + 1];
                    MMA_BF16(acc[m][n], ah[m], b0h, b1h);
                }
        }

        if ((t & 7) == 7) {
            int nc = t >> 3;
#pragma unroll
            for (int n = 0; n < 4; n++) {
                int col0 = nc * 128 + warpN * 32 + n * 8 + tig * 2;
                float e0 = __ldg(&g_e2h[col0]);
                float e1 = __ldg(&g_e2h[col0 + 1]);
#pragma unroll
                for (int m = 0; m < 2; m++)
#pragma unroll
                    for (int h = 0; h < 2; h++) {
                        int slot = m * 2 + h;
                        float s0 = acc[m][n][h * 2 + 0] - e0;
                        float s1 = acc[m][n][h * 2 + 1] - e1;
                        if (s0 > best[slot]) { second[slot] = best[slot]; best[slot] = s0; bidx[slot] = col0; }
                        else if (s0 > second[slot]) second[slot] = s0;
                        if (s1 > best[slot]) { second[slot] = best[slot]; best[slot] = s1; bidx[slot] = col0 + 1; }
                        else if (s1 > second[slot]) second[slot] = s1;
                    }
            }
        }
    }

    __syncthreads();
    float* mb = (float*)smem;          // [128][4]
    float* ms = mb + 512;
    int*   mi = (int*)(ms + 512);
#pragma unroll
    for (int slot = 0; slot < 4; slot++) {
        float b = best[slot], s = second[slot];
        int i = bidx[slot];
#pragma unroll
        for (int off = 1; off <= 2; off <<= 1) {
            float ob = __shfl_xor_sync(0xffffffffu, b, off);
            float os = __shfl_xor_sync(0xffffffffu, s, off);
            int   oi = __shfl_xor_sync(0xffffffffu, i, off);
            if (ob > b || (ob == b && oi < i)) { s = fmaxf(os, b); b = ob; i = oi; }
            else s = fmaxf(s, ob);
        }
        if (tig == 0) {
            int row = warpM * 32 + (slot >> 1) * 16 + gid + (slot & 1) * 8;
            mb[row * 4 + warpN] = b; ms[row * 4 + warpN] = s; mi[row * 4 + warpN] = i;
        }
    }
    __syncthreads();
    if (tid < 128) {
        int row = tid;
        float b = mb[row * 4], s = ms[row * 4];
        int i = mi[row * 4];
#pragma unroll
        for (int w = 1; w < 4; w++) {
            float ob = mb[row * 4 + w], os = ms[row * 4 + w];
            int oi = mi[row * 4 + w];
            if (ob > b || (ob == b && oi < i)) { s = fmaxf(os, b); b = ob; i = oi; }
            else s = fmaxf(s, ob);
        }
        int grow = rowTile * 128 + row;
        g_ind[grow] = i;
        if (b - s < MARGIN) {
            int p = atomicAdd(&g_nflag, 1);
            g_flag[p] = grow;
        }
    }
}

// ---------------- exact fp32 rescue: 16 rows/block, warp per code ----------------
__global__ void __launch_bounds__(512) rescue(const float* __restrict__ x,
                                              const float* __restrict__ embed) {
    __shared__ float xs[RG][512];        // 32KB
    __shared__ float mbv[16][RG];
    __shared__ int   mbi[16][RG];
    int tid = threadIdx.x;
    int w = tid >> 5, lane = tid & 31;
    int nf = g_nflag;
    for (int base = blockIdx.x * RG; base < nf; base += gridDim.x * RG) {
        int cnt = min(RG, nf - base);
        __syncthreads();
        for (int i = tid; i < cnt * 512; i += 512) {
            int r = i >> 9, j = i & 511;
            xs[r][j] = x[(size_t)g_flag[base + r] * 512 + j];
        }
        __syncthreads();
        float bb = -3.4e38f;
        int bi = 0;
        for (int c = w; c < KCODES; c += 16) {
            float acc[RG];
#pragma unroll
            for (int r = 0; r < RG; r++) acc[r] = 0.0f;
            const float4* ep = (const float4*)(embed + (size_t)c * 512);
#pragma unroll
            for (int jj = 0; jj < 4; jj++) {
                float4 e = __ldg(&ep[lane + jj * 32]);
                int j = (lane + jj * 32) * 4;
#pragma unroll
                for (int r = 0; r < RG; r++) {
                    float4 xv = *(float4*)&xs[r][j];
                    acc[r] = fmaf(xv.x, e.x, fmaf(xv.y, e.y,
                              fmaf(xv.z, e.z, fmaf(xv.w, e.w, acc[r]))));
                }
            }
#pragma unroll
            for (int r = 0; r < RG; r++) {
#pragma unroll
                for (int off = 16; off; off >>= 1)
                    acc[r] += __shfl_xor_sync(0xffffffffu, acc[r], off);
            }
            if (lane < cnt) {
                float s = acc[lane] - g_e2h[c];
                if (s > bb || (s == bb && c < bi)) { bb = s; bi = c; }
            }
        }
        if (lane < RG) { mbv[w][lane] = bb; mbi[w][lane] = bi; }
        __syncthreads();
        if (tid < cnt) {
            float b = mbv[0][tid]; int i = mbi[0][tid];
#pragma unroll
            for (int ww = 1; ww < 16; ww++) {
                float ob = mbv[ww][tid]; int oi = mbi[ww][tid];
                if (ob > b || (ob == b && oi < i)) { b = ob; i = oi; }
            }
            g_ind[g_flag[base + tid]] = i;
        }
    }
}

// ---------------- quant gather + per-code counting ----------------
__global__ void quant_gather(const float* __restrict__ embed,
                             float* __restrict__ quant,
                             float* __restrict__ eind) {
    int row = blockIdx.x;
    int k = g_ind[row];
    if (threadIdx.x == 0) {
        g_poslist[row] = atomicAdd(&g_cnt[k], 1);
        eind[row] = (float)k;
    }
    int c = threadIdx.x;
    float4 ev = *(const float4*)(embed + (size_t)k * D + c * 4);
    *(float4*)(quant + (size_t)row * D + c * 4) = ev;
}

__global__ void scan_counts() {
    int k = threadIdx.x;
    __shared__ int s[1024];
    int my = g_cnt[k];
    s[k] = my;
    __syncthreads();
#pragma unroll
    for (int off = 1; off < 1024; off <<= 1) {
        int v = (k >= off) ? s[k - off] : 0;
        __syncthreads();
        s[k] += v;
        __syncthreads();
    }
    g_off[k] = s[k] - my;
    g_counts[k] = (float)my;
}

__global__ void fill_rowlist() {
    int row = blockIdx.x * blockDim.x + threadIdx.x;
    int k = g_ind[row];
    g_rowlist[g_off[k] + g_poslist[row]] = row;
}

__global__ void sum_by_code(const float* __restrict__ x) {
    int c = blockIdx.x;
    int n = g_cnt[c], off = g_off[c];
    int col = threadIdx.x * 4;
    float4 acc = {0.f, 0.f, 0.f, 0.f};
    for (int i = 0; i < n; i++) {
        int row = __ldg(&g_rowlist[off + i]);
        float4 v = *(const float4*)(x + (size_t)row * D + col);
        acc.x += v.x; acc.y += v.y; acc.z += v.z; acc.w += v.w;
    }
    *(float4*)(g_embed_sum + (size_t)c * D + col) = acc;
}

// ---------------- EMA epilogues ----------------
__global__ void ema_cs(const float* __restrict__ cluster_size,
                       float* __restrict__ ncs_out) {
    int k = threadIdx.x;
    float ncs = cluster_size[k] * DECAY + ONE_MINUS_DECAY * g_counts[k];
    ncs_out[k] = ncs;
    __shared__ float sh[1024];
    sh[k] = ncs;
    __syncthreads();
#pragma unroll
    for (int s = 512; s > 0; s >>= 1) {
        if (k < s) sh[k] += sh[k + s];
        __syncthreads();
    }
    float n = sh[0];
    g_cs[k] = (ncs + EPSF) / (n + (float)KCODES * EPSF) * n;
}

__global__ void ema_embed(const float* __restrict__ embed_avg,
                          float* __restrict__ nea_out,
                          float* __restrict__ ne_out) {
    int idx = blockIdx.x * blockDim.x + threadIdx.x;
    if (idx >= KCODES * D) return;
    float nea = embed_avg[idx] * DECAY + ONE_MINUS_DECAY * g_embed_sum[idx];
    nea_out[idx] = nea;
    ne_out[idx] = nea / g_cs[idx >> 9];
}

// ---------------- launch ----------------
extern "C" void kernel_launch(void* const* d_in, const int* in_sizes, int n_in,
                              void* d_out, int out_size) {
    const float* x = (const float*)d_in[0];
    const float* embed = (const float*)d_in[1];
    const float* cluster_size = (const float*)d_in[2];
    const float* embed_avg = (const float*)d_in[3];

    float* out = (float*)d_out;
    float* quant = out;
    float* eind  = quant + (size_t)NROWS * D;
    float* ncs   = eind + NROWS;
    float* nea   = ncs + KCODES;
    float* ne    = nea + (size_t)KCODES * D;

    cudaFuncSetAttribute(gemm_hmma, cudaFuncAttributeMaxDynamicSharedMemorySize, SMEM_TOTAL);

    // order chosen so the GEMM is launch #4 (the one ncu has been capturing)
    compute_e2h<<<KCODES, 128>>>(embed);      // #1 (also zeroes g_cnt/g_nflag)
    convert_x<<<NROWS * (D / 2) / 256, 256>>>(x);        // #2
    convert_b<<<KCODES * (D / 2) / 256, 256>>>(embed);   // #3
    gemm_hmma<<<ROWTILES, 512, SMEM_TOTAL>>>();          // #4  <-- profile target
    rescue<<<166, 512>>>(x, embed);                      // #5
    quant_gather<<<NROWS, 128>>>(embed, quant, eind);    // #6
    scan_counts<<<1, 1024>>>();                          // #7
    fill_rowlist<<<NROWS / 256, 256>>>();                // #8
    sum_by_code<<<KCODES, 128>>>(x);                     // #9
    ema_cs<<<1, 1024>>>(cluster_size, ncs);              // #10
    ema_embed<<<(KCODES * D + 255) / 256, 256>>>(embed_avg, nea, ne);  // #11
}

// round 8
// speedup vs baseline: 1.9965x; 1.1320x over previous
#include <cuda_runtime.h>
#include <cuda_fp16.h>
#include <cstdint>

#define DECAY 0.99f
#define ONE_MINUS_DECAY 0.01f
#define EPSF 1e-5f
#define D 512
#define KCODES 1024
#define NROWS 65536
#define ROWTILES (NROWS / 128)   // 512
#define NTILES 64                // 8 n-chunks * 8 k-tiles (BK=64)
#define STAGE_BYTES 32768        // A/B each 128x64 fp16 = 16KB
#define NSTAGES 4
#define SMEM_TOTAL (NSTAGES * STAGE_BYTES)   // 128KB
#define MARGIN 0.15f
#define RG 16                    // rescue rows per block

// ---------------- device scratch ----------------
__device__ unsigned g_xhi[NROWS * D / 2];     // fp16 pairs
__device__ unsigned g_bhi[KCODES * D / 2];    // fp16 pairs
__device__ float g_e2h[KCODES];   // 0.5*|e|^2
__device__ float g_counts[KCODES];
__device__ float g_embed_sum[KCODES * D];
__device__ int   g_ind[NROWS];
__device__ float g_cs[KCODES];
__device__ int   g_flag[NROWS];
__device__ int   g_nflag;
__device__ int   g_cnt[KCODES];
__device__ int   g_off[KCODES];
__device__ int   g_poslist[NROWS];
__device__ int   g_rowlist[NROWS];

// ---------------- PTX helpers ----------------
__device__ __forceinline__ uint32_t smem_u32(const void* p) {
    uint32_t a;
    asm("{ .reg .u64 t; cvta.to.shared.u64 t, %1; cvt.u32.u64 %0, t; }" : "=r"(a) : "l"(p));
    return a;
}
#define CP_ASYNC16(soff, gptr) \
    asm volatile("cp.async.cg.shared.global [%0], [%1], 16;" \
                 :: "r"(soff), "l"(__cvta_generic_to_global(gptr)))
#define CP_COMMIT() asm volatile("cp.async.commit_group;" ::: "memory")
#define CP_WAIT2() asm volatile("cp.async.wait_group 2;" ::: "memory")

#define LDMX4(r, addr) \
    asm volatile("ldmatrix.sync.aligned.m8n8.x4.shared.b16 {%0,%1,%2,%3}, [%4];" \
                 : "=r"((r)[0]), "=r"((r)[1]), "=r"((r)[2]), "=r"((r)[3]) : "r"(addr))

#define MMA_F16(c, a, b0, b1) \
    asm volatile("mma.sync.aligned.m16n8k16.row.col.f32.f16.f16.f32 " \
                 "{%0,%1,%2,%3}, {%4,%5,%6,%7}, {%8,%9}, {%0,%1,%2,%3};" \
                 : "+f"((c)[0]), "+f"((c)[1]), "+f"((c)[2]), "+f"((c)[3]) \
                 : "r"((a)[0]), "r"((a)[1]), "r"((a)[2]), "r"((a)[3]), "r"(b0), "r"(b1))

__device__ __forceinline__ unsigned pack2h(float a, float b) {
    __half2 h = __floats2half2_rn(a, b);
    return *(unsigned*)&h;
}

// ---------------- prep B: convert embed to fp16 + e2h + zero fold (launch #1) ----------------
__global__ void prep_b(const float* __restrict__ embed) {
    int k = blockIdx.x;        // code
    int t = threadIdx.x;       // 256 threads, one float2 each
    if (t == 0) g_cnt[k] = 0;
    if (k == 0 && t == 1) g_nflag = 0;
    float2 v = *(const float2*)(embed + (size_t)k * D + t * 2);
    g_bhi[k * 256 + t] = pack2h(v.x, v.y);
    float s = v.x * v.x + v.y * v.y;
#pragma unroll
    for (int off = 16; off; off >>= 1) s += __shfl_down_sync(0xffffffffu, s, off);
    __shared__ float sh[8];
    if ((t & 31) == 0) sh[t >> 5] = s;
    __syncthreads();
    if (t == 0) {
        float tot = 0.0f;
#pragma unroll
        for (int i = 0; i < 8; i++) tot += sh[i];
        g_e2h[k] = 0.5f * tot;
    }
}

// ---------------- convert x to fp16 (launch #2) ----------------
__global__ void convert_x(const float* __restrict__ x) {
    size_t i = (size_t)blockIdx.x * blockDim.x + threadIdx.x;
    float2 v = *(const float2*)(x + i * 2);
    g_xhi[i] = pack2h(v.x, v.y);
}

// ---------------- HMMA GEMM (fp16, BK=64) + fused argmax (launch #3) ----------------
// 512 threads = 16 warps (4M x 4N), warp tile 32x32, block tile 128x128, BK=64.
__global__ void __launch_bounds__(512, 1) gemm_hmma() {
    extern __shared__ char smem[];
    uint32_t sb = smem_u32(smem);
    const int tid = threadIdx.x;
    const int lane = tid & 31;
    const int warpM = (tid >> 5) >> 2;   // 0..3
    const int warpN = (tid >> 5) & 3;    // 0..3
    const int gid = lane >> 2, tig = lane & 3;
    const int rowTile = blockIdx.x;

    float acc[2][4][4];
    float best[4], second[4];
    int bidx[4];
#pragma unroll
    for (int s = 0; s < 4; s++) { best[s] = -3.4e38f; second[s] = -3.4e38f; bidx[s] = 0; }

    auto issue = [&](int t) {
        int nc = t >> 3, kt = t & 7;
        uint32_t st = sb + (t & (NSTAGES - 1)) * STAGE_BYTES;
#pragma unroll
        for (int i = 0; i < 4; i++) {
            int idx = tid + i * 512;           // 0..2047
            int mat = idx >> 10;               // 0 A, 1 B
            int id2 = idx & 1023;
            int row = id2 >> 3, g = id2 & 7;
            uint32_t soff = st + mat * 16384 + row * 128 + ((g ^ (row & 7)) << 4);
            size_t goff = (mat == 0)
                ? ((size_t)(rowTile * 128 + row) * D + kt * 64 + g * 8) >> 1
                : ((size_t)(nc * 128 + row) * D + kt * 64 + g * 8) >> 1;
            const unsigned* gp = (mat == 0) ? g_xhi + goff : g_bhi + goff;
            CP_ASYNC16(soff, gp);
        }
        CP_COMMIT();
    };

    issue(0); issue(1); issue(2);

    for (int t = 0; t < NTILES; t++) {
        CP_WAIT2();
        __syncthreads();
        if (t + 3 < NTILES) issue(t + 3); else CP_COMMIT();

        if ((t & 7) == 0) {
#pragma unroll
            for (int m = 0; m < 2; m++)
#pragma unroll
                for (int n = 0; n < 4; n++)
#pragma unroll
                    for (int j = 0; j < 4; j++) acc[m][n][j] = 0.0f;
        }

        uint32_t st = sb + (t & (NSTAGES - 1)) * STAGE_BYTES;
#pragma unroll
        for (int ks = 0; ks < 4; ks++) {
            uint32_t ah[2][4], bh[2][4];
#pragma unroll
            for (int m = 0; m < 2; m++) {
                int r = warpM * 32 + m * 16 + (lane & 15);
                int kc = ks * 2 + (lane >> 4);
                uint32_t a = st + r * 128 + ((kc ^ (r & 7)) << 4);
                LDMX4(ah[m], a);
            }
#pragma unroll
            for (int p = 0; p < 2; p++) {
                int grp = lane >> 3;
                int nt = p * 2 + (grp >> 1);
                int kc = ks * 2 + (grp & 1);
                int r = warpN * 32 + nt * 8 + (lane & 7);
                uint32_t a = st + 16384 + r * 128 + ((kc ^ (r & 7)) << 4);
                LDMX4(bh[p], a);
            }
#pragma unroll
            for (int m = 0; m < 2; m++)
#pragma unroll
                for (int n = 0; n < 4; n++) {
                    uint32_t b0h = bh[n >> 1][(n & 1) * 2], b1h = bh[n >> 1][(n & 1) * 2 + 1];
                    MMA_F16(acc[m][n], ah[m], b0h, b1h);
                }
        }

        if ((t & 7) == 7) {
            int nc = t >> 3;
#pragma unroll
            for (int n = 0; n < 4; n++) {
                int col0 = nc * 128 + warpN * 32 + n * 8 + tig * 2;
                float e0 = __ldg(&g_e2h[col0]);
                float e1 = __ldg(&g_e2h[col0 + 1]);
#pragma unroll
                for (int m = 0; m < 2; m++)
#pragma unroll
                    for (int h = 0; h < 2; h++) {
                        int slot = m * 2 + h;
                        float s0 = acc[m][n][h * 2 + 0] - e0;
                        float s1 = acc[m][n][h * 2 + 1] - e1;
                        if (s0 > best[slot]) { second[slot] = best[slot]; best[slot] = s0; bidx[slot] = col0; }
                        else if (s0 > second[slot]) second[slot] = s0;
                        if (s1 > best[slot]) { second[slot] = best[slot]; best[slot] = s1; bidx[slot] = col0 + 1; }
                        else if (s1 > second[slot]) second[slot] = s1;
                    }
            }
        }
    }

    __syncthreads();
    float* mb = (float*)smem;          // [128][4]
    float* ms = mb + 512;
    int*   mi = (int*)(ms + 512);
#pragma unroll
    for (int slot = 0; slot < 4; slot++) {
        float b = best[slot], s = second[slot];
        int i = bidx[slot];
#pragma unroll
        for (int off = 1; off <= 2; off <<= 1) {
            float ob = __shfl_xor_sync(0xffffffffu, b, off);
            float os = __shfl_xor_sync(0xffffffffu, s, off);
            int   oi = __shfl_xor_sync(0xffffffffu, i, off);
            if (ob > b || (ob == b && oi < i)) { s = fmaxf(os, b); b = ob; i = oi; }
            else s = fmaxf(s, ob);
        }
        if (tig == 0) {
            int row = warpM * 32 + (slot >> 1) * 16 + gid + (slot & 1) * 8;
            mb[row * 4 + warpN] = b; ms[row * 4 + warpN] = s; mi[row * 4 + warpN] = i;
        }
    }
    __syncthreads();
    if (tid < 128) {
        int row = tid;
        float b = mb[row * 4], s = ms[row * 4];
        int i = mi[row * 4];
#pragma unroll
        for (int w = 1; w < 4; w++) {
            float ob = mb[row * 4 + w], os = ms[row * 4 + w];
            int oi = mi[row * 4 + w];
            if (ob > b || (ob == b && oi < i)) { s = fmaxf(os, b); b = ob; i = oi; }
            else s = fmaxf(s, ob);
        }
        int grow = rowTile * 128 + row;
        g_ind[grow] = i;
        if (b - s < MARGIN) {
            int p = atomicAdd(&g_nflag, 1);
            g_flag[p] = grow;
        }
    }
}

// ---------------- exact fp32 rescue (launch #4 <-- profiled) ----------------
__global__ void __launch_bounds__(512) rescue(const float* __restrict__ x,
                                              const float* __restrict__ embed) {
    __shared__ float xs[RG][512];        // 32KB
    __shared__ float mbv[16][RG];
    __shared__ int   mbi[16][RG];
    int tid = threadIdx.x;
    int w = tid >> 5, lane = tid & 31;
    int nf = g_nflag;
    for (int base = blockIdx.x * RG; base < nf; base += gridDim.x * RG) {
        int cnt = min(RG, nf - base);
        __syncthreads();
        for (int i = tid; i < cnt * 512; i += 512) {
            int r = i >> 9, j = i & 511;
            xs[r][j] = x[(size_t)g_flag[base + r] * 512 + j];
        }
        __syncthreads();
        float bb = -3.4e38f;
        int bi = 0;
        for (int c = w; c < KCODES; c += 16) {
            float acc[RG];
#pragma unroll
            for (int r = 0; r < RG; r++) acc[r] = 0.0f;
            const float4* ep = (const float4*)(embed + (size_t)c * 512);
#pragma unroll
            for (int jj = 0; jj < 4; jj++) {
                float4 e = __ldg(&ep[lane + jj * 32]);
                int j = (lane + jj * 32) * 4;
#pragma unroll
                for (int r = 0; r < RG; r++) {
                    float4 xv = *(float4*)&xs[r][j];
                    acc[r] = fmaf(xv.x, e.x, fmaf(xv.y, e.y,
                              fmaf(xv.z, e.z, fmaf(xv.w, e.w, acc[r]))));
                }
            }
#pragma unroll
            for (int r = 0; r < RG; r++) {
#pragma unroll
                for (int off = 16; off; off >>= 1)
                    acc[r] += __shfl_xor_sync(0xffffffffu, acc[r], off);
            }
            if (lane < cnt) {
                float s = acc[lane] - g_e2h[c];
                if (s > bb || (s == bb && c < bi)) { bb = s; bi = c; }
            }
        }
        if (lane < RG) { mbv[w][lane] = bb; mbi[w][lane] = bi; }
        __syncthreads();
        if (tid < cnt) {
            float b = mbv[0][tid]; int i = mbi[0][tid];
#pragma unroll
            for (int ww = 1; ww < 16; ww++) {
                float ob = mbv[ww][tid]; int oi = mbi[ww][tid];
                if (ob > b || (ob == b && oi < i)) { b = ob; i = oi; }
            }
            g_ind[g_flag[base + tid]] = i;
        }
    }
}

// ---------------- quant gather + per-code counting ----------------
__global__ void quant_gather(const float* __restrict__ embed,
                             float* __restrict__ quant,
                             float* __restrict__ eind) {
    int row = blockIdx.x;
    int k = g_ind[row];
    if (threadIdx.x == 0) {
        g_poslist[row] = atomicAdd(&g_cnt[k], 1);
        eind[row] = (float)k;
    }
    int c = threadIdx.x;
    float4 ev = *(const float4*)(embed + (size_t)k * D + c * 4);
    *(float4*)(quant + (size_t)row * D + c * 4) = ev;
}

__global__ void scan_counts() {
    int k = threadIdx.x;
    __shared__ int s[1024];
    int my = g_cnt[k];
    s[k] = my;
    __syncthreads();
#pragma unroll
    for (int off = 1; off < 1024; off <<= 1) {
        int v = (k >= off) ? s[k - off] : 0;
        __syncthreads();
        s[k] += v;
        __syncthreads();
    }
    g_off[k] = s[k] - my;
    g_counts[k] = (float)my;
}

__global__ void fill_rowlist() {
    int row = blockIdx.x * blockDim.x + threadIdx.x;
    int k = g_ind[row];
    g_rowlist[g_off[k] + g_poslist[row]] = row;
}

__global__ void sum_by_code(const float* __restrict__ x) {
    int c = blockIdx.x;
    int n = g_cnt[c], off = g_off[c];
    int col = threadIdx.x * 4;
    float4 acc = {0.f, 0.f, 0.f, 0.f};
    for (int i = 0; i < n; i++) {
        int row = __ldg(&g_rowlist[off + i]);
        float4 v = *(const float4*)(x + (size_t)row * D + col);
        acc.x += v.x; acc.y += v.y; acc.z += v.z; acc.w += v.w;
    }
    *(float4*)(g_embed_sum + (size_t)c * D + col) = acc;
}

// ---------------- EMA epilogues ----------------
__global__ void ema_cs(const float* __restrict__ cluster_size,
                       float* __restrict__ ncs_out) {
    int k = threadIdx.x;
    float ncs = cluster_size[k] * DECAY + ONE_MINUS_DECAY * g_counts[k];
    ncs_out[k] = ncs;
    __shared__ float sh[1024];
    sh[k] = ncs;
    __syncthreads();
#pragma unroll
    for (int s = 512; s > 0; s >>= 1) {
        if (k < s) sh[k] += sh[k + s];
        __syncthreads();
    }
    float n = sh[0];
    g_cs[k] = (ncs + EPSF) / (n + (float)KCODES * EPSF) * n;
}

__global__ void ema_embed(const float* __restrict__ embed_avg,
                          float* __restrict__ nea_out,
                          float* __restrict__ ne_out) {
    int idx = blockIdx.x * blockDim.x + threadIdx.x;
    if (idx >= KCODES * D) return;
    float nea = embed_avg[idx] * DECAY + ONE_MINUS_DECAY * g_embed_sum[idx];
    nea_out[idx] = nea;
    ne_out[idx] = nea / g_cs[idx >> 9];
}

// ---------------- launch ----------------
extern "C" void kernel_launch(void* const* d_in, const int* in_sizes, int n_in,
                              void* d_out, int out_size) {
    const float* x = (const float*)d_in[0];
    const float* embed = (const float*)d_in[1];
    const float* cluster_size = (const float*)d_in[2];
    const float* embed_avg = (const float*)d_in[3];

    float* out = (float*)d_out;
    float* quant = out;
    float* eind  = quant + (size_t)NROWS * D;
    float* ncs   = eind + NROWS;
    float* nea   = ncs + KCODES;
    float* ne    = nea + (size_t)KCODES * D;

    cudaFuncSetAttribute(gemm_hmma, cudaFuncAttributeMaxDynamicSharedMemorySize, SMEM_TOTAL);

    prep_b<<<KCODES, 256>>>(embed);                      // #1 (e2h + convert_b + zeroing)
    convert_x<<<NROWS * (D / 2) / 256, 256>>>(x);        // #2
    gemm_hmma<<<ROWTILES, 512, SMEM_TOTAL>>>();          // #3
    rescue<<<166, 512>>>(x, embed);                      // #4  <-- profile target
    quant_gather<<<NROWS, 128>>>(embed, quant, eind);    // #5
    scan_counts<<<1, 1024>>>();                          // #6
    fill_rowlist<<<NROWS / 256, 256>>>();                // #7
    sum_by_code<<<KCODES, 128>>>(x);                     // #8
    ema_cs<<<1, 1024>>>(cluster_size, ncs);              // #9
    ema_embed<<<(KCODES * D + 255) / 256, 256>>>(embed_avg, nea, ne);  // #10
}

// round 9
// speedup vs baseline: 2.2783x; 1.1411x over previous
#include <cuda_runtime.h>
#include <cuda_fp16.h>
#include <cstdint>

#define DECAY 0.99f
#define ONE_MINUS_DECAY 0.01f
#define EPSF 1e-5f
#define D 512
#define KCODES 1024
#define NROWS 65536
#define ROWTILES (NROWS / 128)   // 512
#define NTILES 64                // 8 n-chunks * 8 k-tiles (BK=64)
#define STAGE_BYTES 32768        // A/B each 128x64 fp16 = 16KB
#define NSTAGES 4
#define SMEM_TOTAL (NSTAGES * STAGE_BYTES)   // 128KB
#define MARGIN 0.05f

// ---------------- device scratch ----------------
__device__ unsigned g_xhi[NROWS * D / 2];     // fp16 pairs
__device__ unsigned g_bhi[KCODES * D / 2];    // fp16 pairs
__device__ float g_e2h[KCODES];   // 0.5*|e|^2
__device__ int   g_ind[NROWS];
__device__ float g_cs[KCODES];
__device__ int   g_flag[NROWS];
__device__ int   g_nflag;
__device__ int   g_cnt[KCODES];
__device__ int   g_off[KCODES];
__device__ int   g_poslist[NROWS];
__device__ int   g_rowlist[NROWS];
__device__ unsigned long long g_best[NROWS];

// ---------------- PTX helpers ----------------
__device__ __forceinline__ uint32_t smem_u32(const void* p) {
    uint32_t a;
    asm("{ .reg .u64 t; cvta.to.shared.u64 t, %1; cvt.u32.u64 %0, t; }" : "=r"(a) : "l"(p));
    return a;
}
#define CP_ASYNC16(soff, gptr) \
    asm volatile("cp.async.cg.shared.global [%0], [%1], 16;" \
                 :: "r"(soff), "l"(__cvta_generic_to_global(gptr)))
#define CP_COMMIT() asm volatile("cp.async.commit_group;" ::: "memory")
#define CP_WAIT2() asm volatile("cp.async.wait_group 2;" ::: "memory")

#define LDMX4(r, addr) \
    asm volatile("ldmatrix.sync.aligned.m8n8.x4.shared.b16 {%0,%1,%2,%3}, [%4];" \
                 : "=r"((r)[0]), "=r"((r)[1]), "=r"((r)[2]), "=r"((r)[3]) : "r"(addr))

#define MMA_F16(c, a, b0, b1) \
    asm volatile("mma.sync.aligned.m16n8k16.row.col.f32.f16.f16.f32 " \
                 "{%0,%1,%2,%3}, {%4,%5,%6,%7}, {%8,%9}, {%0,%1,%2,%3};" \
                 : "+f"((c)[0]), "+f"((c)[1]), "+f"((c)[2]), "+f"((c)[3]) \
                 : "r"((a)[0]), "r"((a)[1]), "r"((a)[2]), "r"((a)[3]), "r"(b0), "r"(b1))

__device__ __forceinline__ unsigned pack2h(float a, float b) {
    __half2 h = __floats2half2_rn(a, b);
    return *(unsigned*)&h;
}

// ---------------- #1 prep B: convert embed fp16 + e2h + zero fold ----------------
__global__ void prep_b(const float* __restrict__ embed) {
    int k = blockIdx.x;
    int t = threadIdx.x;       // 256 threads, one float2 each
    if (t == 0) g_cnt[k] = 0;
    if (k == 0 && t == 1) g_nflag = 0;
    float2 v = *(const float2*)(embed + (size_t)k * D + t * 2);
    g_bhi[k * 256 + t] = pack2h(v.x, v.y);
    float s = v.x * v.x + v.y * v.y;
#pragma unroll
    for (int off = 16; off; off >>= 1) s += __shfl_down_sync(0xffffffffu, s, off);
    __shared__ float sh[8];
    if ((t & 31) == 0) sh[t >> 5] = s;
    __syncthreads();
    if (t == 0) {
        float tot = 0.0f;
#pragma unroll
        for (int i = 0; i < 8; i++) tot += sh[i];
        g_e2h[k] = 0.5f * tot;
    }
}

// ---------------- #2 convert x to fp16 (grid-stride float4) ----------------
__global__ void convert_x(const float* __restrict__ x) {
    const float4* x4 = (const float4*)x;
    uint2* o = (uint2*)g_xhi;
    for (size_t i = (size_t)blockIdx.x * blockDim.x + threadIdx.x;
         i < (size_t)NROWS * D / 4; i += (size_t)gridDim.x * blockDim.x) {
        float4 v = x4[i];
        o[i] = make_uint2(pack2h(v.x, v.y), pack2h(v.z, v.w));
    }
}

// ---------------- #3 HMMA GEMM (fp16, BK=64) + fused argmax ----------------
__global__ void __launch_bounds__(512, 1) gemm_hmma() {
    extern __shared__ char smem[];
    uint32_t sb = smem_u32(smem);
    const int tid = threadIdx.x;
    const int lane = tid & 31;
    const int warpM = (tid >> 5) >> 2;   // 0..3
    const int warpN = (tid >> 5) & 3;    // 0..3
    const int gid = lane >> 2, tig = lane & 3;
    const int rowTile = blockIdx.x;

    float acc[2][4][4];
    float best[4], second[4];
    int bidx[4];
#pragma unroll
    for (int s = 0; s < 4; s++) { best[s] = -3.4e38f; second[s] = -3.4e38f; bidx[s] = 0; }

    auto issue = [&](int t) {
        int nc = t >> 3, kt = t & 7;
        uint32_t st = sb + (t & (NSTAGES - 1)) * STAGE_BYTES;
#pragma unroll
        for (int i = 0; i < 4; i++) {
            int idx = tid + i * 512;           // 0..2047
            int mat = idx >> 10;               // 0 A, 1 B
            int id2 = idx & 1023;
            int row = id2 >> 3, g = id2 & 7;
            uint32_t soff = st + mat * 16384 + row * 128 + ((g ^ (row & 7)) << 4);
            size_t goff = (mat == 0)
                ? ((size_t)(rowTile * 128 + row) * D + kt * 64 + g * 8) >> 1
                : ((size_t)(nc * 128 + row) * D + kt * 64 + g * 8) >> 1;
            const unsigned* gp = (mat == 0) ? g_xhi + goff : g_bhi + goff;
            CP_ASYNC16(soff, gp);
        }
        CP_COMMIT();
    };

    issue(0); issue(1); issue(2);

    for (int t = 0; t < NTILES; t++) {
        CP_WAIT2();
        __syncthreads();
        if (t + 3 < NTILES) issue(t + 3); else CP_COMMIT();

        if ((t & 7) == 0) {
#pragma unroll
            for (int m = 0; m < 2; m++)
#pragma unroll
                for (int n = 0; n < 4; n++)
#pragma unroll
                    for (int j = 0; j < 4; j++) acc[m][n][j] = 0.0f;
        }

        uint32_t st = sb + (t & (NSTAGES - 1)) * STAGE_BYTES;
#pragma unroll
        for (int ks = 0; ks < 4; ks++) {
            uint32_t ah[2][4], bh[2][4];
#pragma unroll
            for (int m = 0; m < 2; m++) {
                int r = warpM * 32 + m * 16 + (lane & 15);
                int kc = ks * 2 + (lane >> 4);
                uint32_t a = st + r * 128 + ((kc ^ (r & 7)) << 4);
                LDMX4(ah[m], a);
            }
#pragma unroll
            for (int p = 0; p < 2; p++) {
                int grp = lane >> 3;
                int nt = p * 2 + (grp >> 1);
                int kc = ks * 2 + (grp & 1);
                int r = warpN * 32 + nt * 8 + (lane & 7);
                uint32_t a = st + 16384 + r * 128 + ((kc ^ (r & 7)) << 4);
                LDMX4(bh[p], a);
            }
#pragma unroll
            for (int m = 0; m < 2; m++)
#pragma unroll
                for (int n = 0; n < 4; n++) {
                    uint32_t b0h = bh[n >> 1][(n & 1) * 2], b1h = bh[n >> 1][(n & 1) * 2 + 1];
                    MMA_F16(acc[m][n], ah[m], b0h, b1h);
                }
        }

        if ((t & 7) == 7) {
            int nc = t >> 3;
#pragma unroll
            for (int n = 0; n < 4; n++) {
                int col0 = nc * 128 + warpN * 32 + n * 8 + tig * 2;
                float e0 = __ldg(&g_e2h[col0]);
                float e1 = __ldg(&g_e2h[col0 + 1]);
#pragma unroll
                for (int m = 0; m < 2; m++)
#pragma unroll
                    for (int h = 0; h < 2; h++) {
                        int slot = m * 2 + h;
                        float s0 = acc[m][n][h * 2 + 0] - e0;
                        float s1 = acc[m][n][h * 2 + 1] - e1;
                        if (s0 > best[slot]) { second[slot] = best[slot]; best[slot] = s0; bidx[slot] = col0; }
                        else if (s0 > second[slot]) second[slot] = s0;
                        if (s1 > best[slot]) { second[slot] = best[slot]; best[slot] = s1; bidx[slot] = col0 + 1; }
                        else if (s1 > second[slot]) second[slot] = s1;
                    }
            }
        }
    }

    __syncthreads();
    float* mb = (float*)smem;          // [128][4]
    float* ms = mb + 512;
    int*   mi = (int*)(ms + 512);
#pragma unroll
    for (int slot = 0; slot < 4; slot++) {
        float b = best[slot], s = second[slot];
        int i = bidx[slot];
#pragma unroll
        for (int off = 1; off <= 2; off <<= 1) {
            float ob = __shfl_xor_sync(0xffffffffu, b, off);
            float os = __shfl_xor_sync(0xffffffffu, s, off);
            int   oi = __shfl_xor_sync(0xffffffffu, i, off);
            if (ob > b || (ob == b && oi < i)) { s = fmaxf(os, b); b = ob; i = oi; }
            else s = fmaxf(s, ob);
        }
        if (tig == 0) {
            int row = warpM * 32 + (slot >> 1) * 16 + gid + (slot & 1) * 8;
            mb[row * 4 + warpN] = b; ms[row * 4 + warpN] = s; mi[row * 4 + warpN] = i;
        }
    }
    __syncthreads();
    if (tid < 128) {
        int row = tid;
        float b = mb[row * 4], s = ms[row * 4];
        int i = mi[row * 4];
#pragma unroll
        for (int w = 1; w < 4; w++) {
            float ob = mb[row * 4 + w], os = ms[row * 4 + w];
            int oi = mi[row * 4 + w];
            if (ob > b || (ob == b && oi < i)) { s = fmaxf(os, b); b = ob; i = oi; }
            else s = fmaxf(s, ob);
        }
        int grow = rowTile * 128 + row;
        g_ind[grow] = i;
        if (b - s < MARGIN) {
            g_best[grow] = 0ull;
            int p = atomicAdd(&g_nflag, 1);
            g_flag[p] = grow;
        }
    }
}

// ---------------- #4 exact fp32 rescue: one block = (flagged row, 1/8 codebook) ----------------
__global__ void __launch_bounds__(256) rescue(const float* __restrict__ x,
                                              const float* __restrict__ embed) {
    __shared__ float4 xs[128];   // the row, 512 floats
    int tid = threadIdx.x;
    int w = tid >> 5, lane = tid & 31;
    int nitems = g_nflag * 8;
    for (int it = blockIdx.x; it < nitems; it += gridDim.x) {
        int row = g_flag[it >> 3];
        int slice = it & 7;
        __syncthreads();
        if (tid < 128) xs[tid] = *((const float4*)(x + (size_t)row * D) + tid);
        __syncthreads();
        float best = -3.4e38f;
        int bc = 0;
#pragma unroll
        for (int i = 0; i < 16; i++) {
            int c = slice * 128 + w * 16 + i;
            const float4* ep = (const float4*)(embed + (size_t)c * D);
            float dot = 0.0f;
#pragma unroll
            for (int p = 0; p < 4; p++) {
                float4 e = __ldg(ep + lane + p * 32);
                float4 xv = xs[lane + p * 32];
                dot = fmaf(xv.x, e.x, fmaf(xv.y, e.y,
                       fmaf(xv.z, e.z, fmaf(xv.w, e.w, dot))));
            }
#pragma unroll
            for (int off = 16; off; off >>= 1)
                dot += __shfl_xor_sync(0xffffffffu, dot, off);
            if (lane == 0) {
                float s = dot - g_e2h[c];
                if (s > best) { best = s; bc = c; }
            }
        }
        if (lane == 0) {
            unsigned bits = __float_as_uint(best);
            unsigned mono = (bits & 0x80000000u) ? ~bits : (bits | 0x80000000u);
            unsigned long long u = ((unsigned long long)mono << 32) | (unsigned)(~bc);
            atomicMax(&g_best[row], u);
        }
    }
}

// ---------------- #5 rescue finalize ----------------
__global__ void rescue_fin() {
    int i = blockIdx.x * blockDim.x + threadIdx.x;
    if (i < g_nflag) {
        int row = g_flag[i];
        g_ind[row] = (int)(~(unsigned)(g_best[row] & 0xffffffffull)) & 1023;
    }
}

// ---------------- #6 count rows (poslist + eind) ----------------
__global__ void count_rows(float* __restrict__ eind) {
    int row = blockIdx.x * blockDim.x + threadIdx.x;
    int k = g_ind[row];
    g_poslist[row] = atomicAdd(&g_cnt[k], 1);
    eind[row] = (float)k;
}

// ---------------- #7 scan + ema_cs fused ----------------
__global__ void scan_counts(const float* __restrict__ cluster_size,
                            float* __restrict__ ncs_out) {
    int k = threadIdx.x;
    __shared__ int s[1024];
    __shared__ float f[1024];
    int my = g_cnt[k];
    s[k] = my;
    __syncthreads();
#pragma unroll
    for (int off = 1; off < 1024; off <<= 1) {
        int v = (k >= off) ? s[k - off] : 0;
        __syncthreads();
        s[k] += v;
        __syncthreads();
    }
    g_off[k] = s[k] - my;
    float ncs = cluster_size[k] * DECAY + ONE_MINUS_DECAY * (float)my;
    ncs_out[k] = ncs;
    f[k] = ncs;
    __syncthreads();
#pragma unroll
    for (int st = 512; st > 0; st >>= 1) {
        if (k < st) f[k] += f[k + st];
        __syncthreads();
    }
    float n = f[0];
    g_cs[k] = (ncs + EPSF) / (n + (float)KCODES * EPSF) * n;
}

// ---------------- #8 fill rowlist ----------------
__global__ void fill_rowlist() {
    int row = blockIdx.x * blockDim.x + threadIdx.x;
    int k = g_ind[row];
    g_rowlist[g_off[k] + g_poslist[row]] = row;
}

// ---------------- #9 quant fill + embed_sum + EMA fused (block per code) ----------------
__global__ void __launch_bounds__(128) quant_sum(const float* __restrict__ x,
                                                 const float* __restrict__ embed,
                                                 const float* __restrict__ embed_avg,
                                                 float* __restrict__ quant,
                                                 float* __restrict__ nea_out,
                                                 float* __restrict__ ne_out) {
    int c = blockIdx.x;
    int t = threadIdx.x;
    int n = g_cnt[c], off = g_off[c];
    float4 e = *((const float4*)(embed + (size_t)c * D) + t);
    float4 acc = {0.f, 0.f, 0.f, 0.f};
    int row = (n > 0) ? __ldg(&g_rowlist[off]) : 0;
    for (int i = 0; i < n; i++) {
        int nrow = (i + 1 < n) ? __ldg(&g_rowlist[off + i + 1]) : 0;
        *((float4*)(quant + (size_t)row * D) + t) = e;
        float4 v = *((const float4*)(x + (size_t)row * D) + t);
        acc.x += v.x; acc.y += v.y; acc.z += v.z; acc.w += v.w;
        row = nrow;
    }
    float4 ea = *((const float4*)(embed_avg + (size_t)c * D) + t);
    float inv = 1.0f / g_cs[c];
    float4 nea, ne;
    nea.x = ea.x * DECAY + ONE_MINUS_DECAY * acc.x; ne.x = nea.x * inv;
    nea.y = ea.y * DECAY + ONE_MINUS_DECAY * acc.y; ne.y = nea.y * inv;
    nea.z = ea.z * DECAY + ONE_MINUS_DECAY * acc.z; ne.z = nea.z * inv;
    nea.w = ea.w * DECAY + ONE_MINUS_DECAY * acc.w; ne.w = nea.w * inv;
    *((float4*)(nea_out + (size_t)c * D) + t) = nea;
    *((float4*)(ne_out + (size_t)c * D) + t) = ne;
}

// ---------------- launch ----------------
extern "C" void kernel_launch(void* const* d_in, const int* in_sizes, int n_in,
                              void* d_out, int out_size) {
    const float* x = (const float*)d_in[0];
    const float* embed = (const float*)d_in[1];
    const float* cluster_size = (const float*)d_in[2];
    const float* embed_avg = (const float*)d_in[3];

    float* out = (float*)d_out;
    float* quant = out;
    float* eind  = quant + (size_t)NROWS * D;
    float* ncs   = eind + NROWS;
    float* nea   = ncs + KCODES;
    float* ne    = nea + (size_t)KCODES * D;

    cudaFuncSetAttribute(gemm_hmma, cudaFuncAttributeMaxDynamicSharedMemorySize, SMEM_TOTAL);

    prep_b<<<KCODES, 256>>>(embed);                      // #1
    convert_x<<<2048, 256>>>(x);                         // #2
    gemm_hmma<<<ROWTILES, 512, SMEM_TOTAL>>>();          // #3
    rescue<<<4096, 256>>>(x, embed);                     // #4  <-- profile target
    rescue_fin<<<16, 256>>>();                           // #5
    count_rows<<<NROWS / 256, 256>>>(eind);              // #6
    scan_counts<<<1, 1024>>>(cluster_size, ncs);         // #7
    fill_rowlist<<<NROWS / 256, 256>>>();                // #8
    quant_sum<<<KCODES, 128>>>(x, embed, embed_avg, quant, nea, ne);  // #9
}

// round 10
// speedup vs baseline: 5.1510x; 2.2609x over previous
#include <cuda_runtime.h>
#include <cuda_fp16.h>
#include <cstdint>

#define DECAY 0.99f
#define ONE_MINUS_DECAY 0.01f
#define EPSF 1e-5f
#define D 512
#define KCODES 1024
#define NROWS 65536
#define ROWTILES (NROWS / 128)   // 512
#define NTILES 64                // 8 n-chunks * 8 k-tiles (BK=64)
#define STAGE_BYTES 32768        // A/B each 128x64 fp16 = 16KB
#define NSTAGES 4
#define SMEM_TOTAL (NSTAGES * STAGE_BYTES)   // 128KB
#define MARGIN 0.05f
#define CH 64                    // rowlist entries per seg_sum block

// ---------------- device scratch ----------------
__device__ unsigned g_xhi[NROWS * D / 2];     // fp16 pairs
__device__ unsigned g_bhi[KCODES * D / 2];    // fp16 pairs
__device__ float g_e2h[KCODES];   // 0.5*|e|^2
__device__ float g_embed_sum[KCODES * D];
__device__ int   g_ind[NROWS];
__device__ float g_cs[KCODES];
__device__ int   g_flag[NROWS];
__device__ int   g_nflag;
__device__ int   g_cnt[KCODES];
__device__ int   g_off[KCODES];
__device__ int   g_poslist[NROWS];
__device__ int   g_rowlist[NROWS];
__device__ unsigned long long g_best[NROWS];

// ---------------- PTX helpers ----------------
__device__ __forceinline__ uint32_t smem_u32(const void* p) {
    uint32_t a;
    asm("{ .reg .u64 t; cvta.to.shared.u64 t, %1; cvt.u32.u64 %0, t; }" : "=r"(a) : "l"(p));
    return a;
}
#define CP_ASYNC16(soff, gptr) \
    asm volatile("cp.async.cg.shared.global [%0], [%1], 16;" \
                 :: "r"(soff), "l"(__cvta_generic_to_global(gptr)))
#define CP_COMMIT() asm volatile("cp.async.commit_group;" ::: "memory")
#define CP_WAIT2() asm volatile("cp.async.wait_group 2;" ::: "memory")

#define LDMX4(r, addr) \
    asm volatile("ldmatrix.sync.aligned.m8n8.x4.shared.b16 {%0,%1,%2,%3}, [%4];" \
                 : "=r"((r)[0]), "=r"((r)[1]), "=r"((r)[2]), "=r"((r)[3]) : "r"(addr))

#define MMA_F16(c, a, b0, b1) \
    asm volatile("mma.sync.aligned.m16n8k16.row.col.f32.f16.f16.f32 " \
                 "{%0,%1,%2,%3}, {%4,%5,%6,%7}, {%8,%9}, {%0,%1,%2,%3};" \
                 : "+f"((c)[0]), "+f"((c)[1]), "+f"((c)[2]), "+f"((c)[3]) \
                 : "r"((a)[0]), "r"((a)[1]), "r"((a)[2]), "r"((a)[3]), "r"(b0), "r"(b1))

__device__ __forceinline__ unsigned pack2h(float a, float b) {
    __half2 h = __floats2half2_rn(a, b);
    return *(unsigned*)&h;
}

// ---------------- #1 prep B: convert embed fp16 + e2h + zero embed_sum/cnt ----------------
__global__ void prep_b(const float* __restrict__ embed) {
    int k = blockIdx.x;
    int t = threadIdx.x;       // 256 threads, one float2 each
    if (t == 0) g_cnt[k] = 0;
    if (k == 0 && t == 1) g_nflag = 0;
    ((float2*)g_embed_sum)[k * 256 + t] = make_float2(0.f, 0.f);
    float2 v = *(const float2*)(embed + (size_t)k * D + t * 2);
    g_bhi[k * 256 + t] = pack2h(v.x, v.y);
    float s = v.x * v.x + v.y * v.y;
#pragma unroll
    for (int off = 16; off; off >>= 1) s += __shfl_down_sync(0xffffffffu, s, off);
    __shared__ float sh[8];
    if ((t & 31) == 0) sh[t >> 5] = s;
    __syncthreads();
    if (t == 0) {
        float tot = 0.0f;
#pragma unroll
        for (int i = 0; i < 8; i++) tot += sh[i];
        g_e2h[k] = 0.5f * tot;
    }
}

// ---------------- #2 convert x to fp16 (grid-stride float4) ----------------
__global__ void convert_x(const float* __restrict__ x) {
    const float4* x4 = (const float4*)x;
    uint2* o = (uint2*)g_xhi;
    for (size_t i = (size_t)blockIdx.x * blockDim.x + threadIdx.x;
         i < (size_t)NROWS * D / 4; i += (size_t)gridDim.x * blockDim.x) {
        float4 v = x4[i];
        o[i] = make_uint2(pack2h(v.x, v.y), pack2h(v.z, v.w));
    }
}

// ---------------- #3 HMMA GEMM (fp16, BK=64) + fused argmax ----------------
__global__ void __launch_bounds__(512, 1) gemm_hmma() {
    extern __shared__ char smem[];
    uint32_t sb = smem_u32(smem);
    const int tid = threadIdx.x;
    const int lane = tid & 31;
    const int warpM = (tid >> 5) >> 2;   // 0..3
    const int warpN = (tid >> 5) & 3;    // 0..3
    const int gid = lane >> 2, tig = lane & 3;
    const int rowTile = blockIdx.x;

    float acc[2][4][4];
    float best[4], second[4];
    int bidx[4];
#pragma unroll
    for (int s = 0; s < 4; s++) { best[s] = -3.4e38f; second[s] = -3.4e38f; bidx[s] = 0; }

    auto issue = [&](int t) {
        int nc = t >> 3, kt = t & 7;
        uint32_t st = sb + (t & (NSTAGES - 1)) * STAGE_BYTES;
#pragma unroll
        for (int i = 0; i < 4; i++) {
            int idx = tid + i * 512;           // 0..2047
            int mat = idx >> 10;               // 0 A, 1 B
            int id2 = idx & 1023;
            int row = id2 >> 3, g = id2 & 7;
            uint32_t soff = st + mat * 16384 + row * 128 + ((g ^ (row & 7)) << 4);
            size_t goff = (mat == 0)
                ? ((size_t)(rowTile * 128 + row) * D + kt * 64 + g * 8) >> 1
                : ((size_t)(nc * 128 + row) * D + kt * 64 + g * 8) >> 1;
            const unsigned* gp = (mat == 0) ? g_xhi + goff : g_bhi + goff;
            CP_ASYNC16(soff, gp);
        }
        CP_COMMIT();
    };

    issue(0); issue(1); issue(2);

    for (int t = 0; t < NTILES; t++) {
        CP_WAIT2();
        __syncthreads();
        if (t + 3 < NTILES) issue(t + 3); else CP_COMMIT();

        if ((t & 7) == 0) {
#pragma unroll
            for (int m = 0; m < 2; m++)
#pragma unroll
                for (int n = 0; n < 4; n++)
#pragma unroll
                    for (int j = 0; j < 4; j++) acc[m][n][j] = 0.0f;
        }

        uint32_t st = sb + (t & (NSTAGES - 1)) * STAGE_BYTES;
#pragma unroll
        for (int ks = 0; ks < 4; ks++) {
            uint32_t ah[2][4], bh[2][4];
#pragma unroll
            for (int m = 0; m < 2; m++) {
                int r = warpM * 32 + m * 16 + (lane & 15);
                int kc = ks * 2 + (lane >> 4);
                uint32_t a = st + r * 128 + ((kc ^ (r & 7)) << 4);
                LDMX4(ah[m], a);
            }
#pragma unroll
            for (int p = 0; p < 2; p++) {
                int grp = lane >> 3;
                int nt = p * 2 + (grp >> 1);
                int kc = ks * 2 + (grp & 1);
                int r = warpN * 32 + nt * 8 + (lane & 7);
                uint32_t a = st + 16384 + r * 128 + ((kc ^ (r & 7)) << 4);
                LDMX4(bh[p], a);
            }
#pragma unroll
            for (int m = 0; m < 2; m++)
#pragma unroll
                for (int n = 0; n < 4; n++) {
                    uint32_t b0h = bh[n >> 1][(n & 1) * 2], b1h = bh[n >> 1][(n & 1) * 2 + 1];
                    MMA_F16(acc[m][n], ah[m], b0h, b1h);
                }
        }

        if ((t & 7) == 7) {
            int nc = t >> 3;
#pragma unroll
            for (int n = 0; n < 4; n++) {
                int col0 = nc * 128 + warpN * 32 + n * 8 + tig * 2;
                float e0 = __ldg(&g_e2h[col0]);
                float e1 = __ldg(&g_e2h[col0 + 1]);
#pragma unroll
                for (int m = 0; m < 2; m++)
#pragma unroll
                    for (int h = 0; h < 2; h++) {
                        int slot = m * 2 + h;
                        float s0 = acc[m][n][h * 2 + 0] - e0;
                        float s1 = acc[m][n][h * 2 + 1] - e1;
                        if (s0 > best[slot]) { second[slot] = best[slot]; best[slot] = s0; bidx[slot] = col0; }
                        else if (s0 > second[slot]) second[slot] = s0;
                        if (s1 > best[slot]) { second[slot] = best[slot]; best[slot] = s1; bidx[slot] = col0 + 1; }
                        else if (s1 > second[slot]) second[slot] = s1;
                    }
            }
        }
    }

    __syncthreads();
    float* mb = (float*)smem;          // [128][4]
    float* ms = mb + 512;
    int*   mi = (int*)(ms + 512);
#pragma unroll
    for (int slot = 0; slot < 4; slot++) {
        float b = best[slot], s = second[slot];
        int i = bidx[slot];
#pragma unroll
        for (int off = 1; off <= 2; off <<= 1) {
            float ob = __shfl_xor_sync(0xffffffffu, b, off);
            float os = __shfl_xor_sync(0xffffffffu, s, off);
            int   oi = __shfl_xor_sync(0xffffffffu, i, off);
            if (ob > b || (ob == b && oi < i)) { s = fmaxf(os, b); b = ob; i = oi; }
            else s = fmaxf(s, ob);
        }
        if (tig == 0) {
            int row = warpM * 32 + (slot >> 1) * 16 + gid + (slot & 1) * 8;
            mb[row * 4 + warpN] = b; ms[row * 4 + warpN] = s; mi[row * 4 + warpN] = i;
        }
    }
    __syncthreads();
    if (tid < 128) {
        int row = tid;
        float b = mb[row * 4], s = ms[row * 4];
        int i = mi[row * 4];
#pragma unroll
        for (int w = 1; w < 4; w++) {
            float ob = mb[row * 4 + w], os = ms[row * 4 + w];
            int oi = mi[row * 4 + w];
            if (ob > b || (ob == b && oi < i)) { s = fmaxf(os, b); b = ob; i = oi; }
            else s = fmaxf(s, ob);
        }
        int grow = rowTile * 128 + row;
        g_ind[grow] = i;
        if (b - s < MARGIN) {
            g_best[grow] = 0ull;
            int p = atomicAdd(&g_nflag, 1);
            g_flag[p] = grow;
        }
    }
}

// ---------------- #4 exact fp32 rescue: one item = (flagged row, 1/8 codebook) ----------------
__global__ void __launch_bounds__(256) rescue(const float* __restrict__ x,
                                              const float* __restrict__ embed) {
    __shared__ float4 xs[128];   // the row, 512 floats
    int tid = threadIdx.x;
    int w = tid >> 5, lane = tid & 31;
    int nitems = g_nflag * 8;
    for (int it = blockIdx.x; it < nitems; it += gridDim.x) {
        int row = g_flag[it >> 3];
        int slice = it & 7;
        __syncthreads();
        if (tid < 128) xs[tid] = *((const float4*)(x + (size_t)row * D) + tid);
        __syncthreads();
        float best = -3.4e38f;
        int bc = 0;
#pragma unroll
        for (int i = 0; i < 16; i++) {
            int c = slice * 128 + w * 16 + i;
            const float4* ep = (const float4*)(embed + (size_t)c * D);
            float dot = 0.0f;
#pragma unroll
            for (int p = 0; p < 4; p++) {
                float4 e = __ldg(ep + lane + p * 32);
                float4 xv = xs[lane + p * 32];
                dot = fmaf(xv.x, e.x, fmaf(xv.y, e.y,
                       fmaf(xv.z, e.z, fmaf(xv.w, e.w, dot))));
            }
#pragma unroll
            for (int off = 16; off; off >>= 1)
                dot += __shfl_xor_sync(0xffffffffu, dot, off);
            if (lane == 0) {
                float s = dot - g_e2h[c];
                if (s > best) { best = s; bc = c; }
            }
        }
        if (lane == 0) {
            unsigned bits = __float_as_uint(best);
            unsigned mono = (bits & 0x80000000u) ? ~bits : (bits | 0x80000000u);
            unsigned long long u = ((unsigned long long)mono << 32) | (unsigned)(~bc);
            atomicMax(&g_best[row], u);
        }
    }
}

// ---------------- #5 rescue finalize ----------------
__global__ void rescue_fin() {
    int i = blockIdx.x * blockDim.x + threadIdx.x;
    if (i < g_nflag) {
        int row = g_flag[i];
        g_ind[row] = (int)(~(unsigned)(g_best[row] & 0xffffffffull)) & 1023;
    }
}

// ---------------- #6 count rows (poslist + eind) ----------------
__global__ void count_rows(float* __restrict__ eind) {
    int row = blockIdx.x * blockDim.x + threadIdx.x;
    int k = g_ind[row];
    g_poslist[row] = atomicAdd(&g_cnt[k], 1);
    eind[row] = (float)k;
}

// ---------------- #7 scan + ema_cs fused ----------------
__global__ void scan_counts(const float* __restrict__ cluster_size,
                            float* __restrict__ ncs_out) {
    int k = threadIdx.x;
    __shared__ int s[1024];
    __shared__ float f[1024];
    int my = g_cnt[k];
    s[k] = my;
    __syncthreads();
#pragma unroll
    for (int off = 1; off < 1024; off <<= 1) {
        int v = (k >= off) ? s[k - off] : 0;
        __syncthreads();
        s[k] += v;
        __syncthreads();
    }
    g_off[k] = s[k] - my;
    float ncs = cluster_size[k] * DECAY + ONE_MINUS_DECAY * (float)my;
    ncs_out[k] = ncs;
    f[k] = ncs;
    __syncthreads();
#pragma unroll
    for (int st = 512; st > 0; st >>= 1) {
        if (k < st) f[k] += f[k + st];
        __syncthreads();
    }
    float n = f[0];
    g_cs[k] = (ncs + EPSF) / (n + (float)KCODES * EPSF) * n;
}

// ---------------- #8 fill rowlist ----------------
__global__ void fill_rowlist() {
    int row = blockIdx.x * blockDim.x + threadIdx.x;
    int k = g_ind[row];
    g_rowlist[g_off[k] + g_poslist[row]] = row;
}

// ---------------- #9 quant fill (row-parallel, skew-immune) ----------------
__global__ void __launch_bounds__(256) quant_fill(const float* __restrict__ embed,
                                                  float* __restrict__ quant) {
    int row = blockIdx.x * 2 + (threadIdx.x >> 7);
    int c = threadIdx.x & 127;
    int k = __ldg(&g_ind[row]);
    float4 e = __ldg((const float4*)(embed + (size_t)k * D) + c);
    *((float4*)(quant + (size_t)row * D) + c) = e;
}

// ---------------- #10 segmented embed_sum over rowlist chunks (skew-immune) ----------------
__global__ void __launch_bounds__(128) seg_sum(const float* __restrict__ x) {
    __shared__ int rows[CH];
    __shared__ int codes[CH];
    int t = threadIdx.x;
    int j0 = blockIdx.x * CH;
    if (t < CH) {
        int r = g_rowlist[j0 + t];
        rows[t] = r;
        codes[t] = g_ind[r];
    }
    __syncthreads();
    float4 acc = {0.f, 0.f, 0.f, 0.f};
#pragma unroll 4
    for (int j = 0; j < CH; j++) {
        float4 v = __ldg((const float4*)(x + (size_t)rows[j] * D) + t);
        acc.x += v.x; acc.y += v.y; acc.z += v.z; acc.w += v.w;
        if (j == CH - 1 || codes[j + 1] != codes[j]) {
            float* es = g_embed_sum + (size_t)codes[j] * D + t * 4;
            atomicAdd(es + 0, acc.x);
            atomicAdd(es + 1, acc.y);
            atomicAdd(es + 2, acc.z);
            atomicAdd(es + 3, acc.w);
            acc = make_float4(0.f, 0.f, 0.f, 0.f);
        }
    }
}

// ---------------- #11 EMA embed (flat) ----------------
__global__ void __launch_bounds__(256) ema_embed(const float* __restrict__ embed_avg,
                                                 float* __restrict__ nea_out,
                                                 float* __restrict__ ne_out) {
    int i = blockIdx.x * 256 + threadIdx.x;   // over KCODES*D/4 float4
    int c = (i * 4) >> 9;
    float4 es = *((const float4*)g_embed_sum + i);
    float4 ea = __ldg((const float4*)embed_avg + i);
    float inv = 1.0f / g_cs[c];
    float4 nea, ne;
    nea.x = ea.x * DECAY + ONE_MINUS_DECAY * es.x; ne.x = nea.x * inv;
    nea.y = ea.y * DECAY + ONE_MINUS_DECAY * es.y; ne.y = nea.y * inv;
    nea.z = ea.z * DECAY + ONE_MINUS_DECAY * es.z; ne.z = nea.z * inv;
    nea.w = ea.w * DECAY + ONE_MINUS_DECAY * es.w; ne.w = nea.w * inv;
    ((float4*)nea_out)[i] = nea;
    ((float4*)ne_out)[i] = ne;
}

// ---------------- launch ----------------
extern "C" void kernel_launch(void* const* d_in, const int* in_sizes, int n_in,
                              void* d_out, int out_size) {
    const float* x = (const float*)d_in[0];
    const float* embed = (const float*)d_in[1];
    const float* cluster_size = (const float*)d_in[2];
    const float* embed_avg = (const float*)d_in[3];

    float* out = (float*)d_out;
    float* quant = out;
    float* eind  = quant + (size_t)NROWS * D;
    float* ncs   = eind + NROWS;
    float* nea   = ncs + KCODES;
    float* ne    = nea + (size_t)KCODES * D;

    cudaFuncSetAttribute(gemm_hmma, cudaFuncAttributeMaxDynamicSharedMemorySize, SMEM_TOTAL);

    prep_b<<<KCODES, 256>>>(embed);                      // #1
    convert_x<<<2048, 256>>>(x);                         // #2
    gemm_hmma<<<ROWTILES, 512, SMEM_TOTAL>>>();          // #3
    rescue<<<4096, 256>>>(x, embed);                     // #4  <-- profile target
    rescue_fin<<<16, 256>>>();                           // #5
    count_rows<<<NROWS / 256, 256>>>(eind);              // #6
    scan_counts<<<1, 1024>>>(cluster_size, ncs);         // #7
    fill_rowlist<<<NROWS / 256, 256>>>();                // #8
    quant_fill<<<NROWS / 2, 256>>>(embed, quant);        // #9
    seg_sum<<<NROWS / CH, 128>>>(x);                     // #10
    ema_embed<<<KCODES * D / 4 / 256, 256>>>(embed_avg, nea, ne);  // #11
}

// round 11
// speedup vs baseline: 5.9569x; 1.1565x over previous
#include <cuda_runtime.h>
#include <cuda_fp16.h>
#include <cstdint>

#define DECAY 0.99f
#define ONE_MINUS_DECAY 0.01f
#define EPSF 1e-5f
#define D 512
#define KCODES 1024
#define NROWS 65536
#define BM 64
#define ROWTILES (NROWS / BM)    // 1024
#define NTILES 64                // 8 n-chunks * 8 k-tiles (BK=64)
#define A_BYTES 8192             // 64x64 fp16
#define B_BYTES 16384            // 128x64 fp16
#define STAGE_BYTES (A_BYTES + B_BYTES)      // 24576
#define NSTAGES 4
#define SMEM_TOTAL (NSTAGES * STAGE_BYTES)   // 98304
#define MARGIN 0.05f
#define CH 64                    // rowlist entries per seg_sum block

// ---------------- device scratch ----------------
__device__ unsigned g_xhi[NROWS * D / 2];     // fp16 pairs
__device__ unsigned g_bhi[KCODES * D / 2];    // fp16 pairs
__device__ float g_e2h[KCODES];   // 0.5*|e|^2
__device__ float g_embed_sum[KCODES * D];
__device__ int   g_ind[NROWS];
__device__ float g_cs[KCODES];
__device__ int   g_flag[NROWS];
__device__ int   g_nflag;
__device__ int   g_cnt[KCODES];
__device__ int   g_off[KCODES];
__device__ int   g_poslist[NROWS];
__device__ int   g_rowlist[NROWS];
__device__ unsigned long long g_best[NROWS];

// ---------------- PTX helpers ----------------
__device__ __forceinline__ uint32_t smem_u32(const void* p) {
    uint32_t a;
    asm("{ .reg .u64 t; cvta.to.shared.u64 t, %1; cvt.u32.u64 %0, t; }" : "=r"(a) : "l"(p));
    return a;
}
#define CP_ASYNC16(soff, gptr) \
    asm volatile("cp.async.cg.shared.global [%0], [%1], 16;" \
                 :: "r"(soff), "l"(__cvta_generic_to_global(gptr)))
#define CP_COMMIT() asm volatile("cp.async.commit_group;" ::: "memory")
#define CP_WAIT2() asm volatile("cp.async.wait_group 2;" ::: "memory")

#define LDMX4(r, addr) \
    asm volatile("ldmatrix.sync.aligned.m8n8.x4.shared.b16 {%0,%1,%2,%3}, [%4];" \
                 : "=r"((r)[0]), "=r"((r)[1]), "=r"((r)[2]), "=r"((r)[3]) : "r"(addr))

#define MMA_F16(c, a, b0, b1) \
    asm volatile("mma.sync.aligned.m16n8k16.row.col.f32.f16.f16.f32 " \
                 "{%0,%1,%2,%3}, {%4,%5,%6,%7}, {%8,%9}, {%0,%1,%2,%3};" \
                 : "+f"((c)[0]), "+f"((c)[1]), "+f"((c)[2]), "+f"((c)[3]) \
                 : "r"((a)[0]), "r"((a)[1]), "r"((a)[2]), "r"((a)[3]), "r"(b0), "r"(b1))

__device__ __forceinline__ unsigned pack2h(float a, float b) {
    __half2 h = __floats2half2_rn(a, b);
    return *(unsigned*)&h;
}

// ---------------- #1 prep B: convert embed fp16 + e2h + zero embed_sum/cnt ----------------
__global__ void prep_b(const float* __restrict__ embed) {
    int k = blockIdx.x;
    int t = threadIdx.x;       // 256 threads, one float2 each
    if (t == 0) g_cnt[k] = 0;
    if (k == 0 && t == 1) g_nflag = 0;
    ((float2*)g_embed_sum)[k * 256 + t] = make_float2(0.f, 0.f);
    float2 v = *(const float2*)(embed + (size_t)k * D + t * 2);
    g_bhi[k * 256 + t] = pack2h(v.x, v.y);
    float s = v.x * v.x + v.y * v.y;
#pragma unroll
    for (int off = 16; off; off >>= 1) s += __shfl_down_sync(0xffffffffu, s, off);
    __shared__ float sh[8];
    if ((t & 31) == 0) sh[t >> 5] = s;
    __syncthreads();
    if (t == 0) {
        float tot = 0.0f;
#pragma unroll
        for (int i = 0; i < 8; i++) tot += sh[i];
        g_e2h[k] = 0.5f * tot;
    }
}

// ---------------- #2/#3 convert x to fp16 (two halves so gemm is launch #4) ----------------
__global__ void convert_x(const float* __restrict__ x, int half) {
    const float4* x4 = (const float4*)x;
    uint2* o = (uint2*)g_xhi;
    size_t base = (size_t)half * (NROWS * D / 8);
    for (size_t i = (size_t)blockIdx.x * blockDim.x + threadIdx.x;
         i < (size_t)NROWS * D / 8; i += (size_t)gridDim.x * blockDim.x) {
        float4 v = x4[base + i];
        o[base + i] = make_uint2(pack2h(v.x, v.y), pack2h(v.z, v.w));
    }
}

// ---------------- #4 HMMA GEMM (fp16, BM=64, BK=64, 2 CTA/SM) + fused argmax ----------------
__global__ void __launch_bounds__(256, 2) gemm_hmma() {
    extern __shared__ char smem[];
    uint32_t sb = smem_u32(smem);
    const int tid = threadIdx.x;
    const int lane = tid & 31;
    const int warpM = (tid >> 5) >> 2;   // 0..1
    const int warpN = (tid >> 5) & 3;    // 0..3
    const int gid = lane >> 2, tig = lane & 3;
    const int rowTile = blockIdx.x;

    float acc[2][4][4];
    float best[4], second[4];
    int bidx[4];
#pragma unroll
    for (int s = 0; s < 4; s++) { best[s] = -3.4e38f; second[s] = -3.4e38f; bidx[s] = 0; }

    auto issue = [&](int t) {
        int nc = t >> 3, kt = t & 7;
        uint32_t st = sb + (t & (NSTAGES - 1)) * STAGE_BYTES;
#pragma unroll
        for (int i = 0; i < 6; i++) {
            int idx = tid + i * 256;           // 0..1535; A: 0..511, B: 512..1535
            int isB = idx >= 512;
            int id2 = idx - (isB << 9);
            int row = id2 >> 3, g = id2 & 7;
            uint32_t soff = st + (isB ? A_BYTES : 0) + row * 128 + ((g ^ (row & 7)) << 4);
            size_t goff = isB
                ? ((size_t)(nc * 128 + row) * D + kt * 64 + g * 8) >> 1
                : ((size_t)(rowTile * BM + row) * D + kt * 64 + g * 8) >> 1;
            const unsigned* gp = isB ? g_bhi + goff : g_xhi + goff;
            CP_ASYNC16(soff, gp);
        }
        CP_COMMIT();
    };

    issue(0); issue(1); issue(2);

    for (int t = 0; t < NTILES; t++) {
        CP_WAIT2();
        __syncthreads();
        if (t + 3 < NTILES) issue(t + 3); else CP_COMMIT();

        if ((t & 7) == 0) {
#pragma unroll
            for (int m = 0; m < 2; m++)
#pragma unroll
                for (int n = 0; n < 4; n++)
#pragma unroll
                    for (int j = 0; j < 4; j++) acc[m][n][j] = 0.0f;
        }

        uint32_t st = sb + (t & (NSTAGES - 1)) * STAGE_BYTES;
#pragma unroll
        for (int ks = 0; ks < 4; ks++) {
            uint32_t ah[2][4], bh[2][4];
#pragma unroll
            for (int m = 0; m < 2; m++) {
                int r = warpM * 32 + m * 16 + (lane & 15);
                int kc = ks * 2 + (lane >> 4);
                uint32_t a = st + r * 128 + ((kc ^ (r & 7)) << 4);
                LDMX4(ah[m], a);
            }
#pragma unroll
            for (int p = 0; p < 2; p++) {
                int grp = lane >> 3;
                int nt = p * 2 + (grp >> 1);
                int kc = ks * 2 + (grp & 1);
                int r = warpN * 32 + nt * 8 + (lane & 7);
                uint32_t a = st + A_BYTES + r * 128 + ((kc ^ (r & 7)) << 4);
                LDMX4(bh[p], a);
            }
#pragma unroll
            for (int m = 0; m < 2; m++)
#pragma unroll
                for (int n = 0; n < 4; n++) {
                    uint32_t b0h = bh[n >> 1][(n & 1) * 2], b1h = bh[n >> 1][(n & 1) * 2 + 1];
                    MMA_F16(acc[m][n], ah[m], b0h, b1h);
                }
        }

        if ((t & 7) == 7) {
            int nc = t >> 3;
#pragma unroll
            for (int n = 0; n < 4; n++) {
                int col0 = nc * 128 + warpN * 32 + n * 8 + tig * 2;
                float e0 = __ldg(&g_e2h[col0]);
                float e1 = __ldg(&g_e2h[col0 + 1]);
#pragma unroll
                for (int m = 0; m < 2; m++)
#pragma unroll
                    for (int h = 0; h < 2; h++) {
                        int slot = m * 2 + h;
                        float s0 = acc[m][n][h * 2 + 0] - e0;
                        float s1 = acc[m][n][h * 2 + 1] - e1;
                        if (s0 > best[slot]) { second[slot] = best[slot]; best[slot] = s0; bidx[slot] = col0; }
                        else if (s0 > second[slot]) second[slot] = s0;
                        if (s1 > best[slot]) { second[slot] = best[slot]; best[slot] = s1; bidx[slot] = col0 + 1; }
                        else if (s1 > second[slot]) second[slot] = s1;
                    }
            }
        }
    }

    __syncthreads();
    float* mb = (float*)smem;          // [64][4]
    float* ms = mb + 256;
    int*   mi = (int*)(ms + 256);
#pragma unroll
    for (int slot = 0; slot < 4; slot++) {
        float b = best[slot], s = second[slot];
        int i = bidx[slot];
#pragma unroll
        for (int off = 1; off <= 2; off <<= 1) {
            float ob = __shfl_xor_sync(0xffffffffu, b, off);
            float os = __shfl_xor_sync(0xffffffffu, s, off);
            int   oi = __shfl_xor_sync(0xffffffffu, i, off);
            if (ob > b || (ob == b && oi < i)) { s = fmaxf(os, b); b = ob; i = oi; }
            else s = fmaxf(s, ob);
        }
        if (tig == 0) {
            int row = warpM * 32 + (slot >> 1) * 16 + gid + (slot & 1) * 8;
            mb[row * 4 + warpN] = b; ms[row * 4 + warpN] = s; mi[row * 4 + warpN] = i;
        }
    }
    __syncthreads();
    if (tid < BM) {
        int row = tid;
        float b = mb[row * 4], s = ms[row * 4];
        int i = mi[row * 4];
#pragma unroll
        for (int w = 1; w < 4; w++) {
            float ob = mb[row * 4 + w], os = ms[row * 4 + w];
            int oi = mi[row * 4 + w];
            if (ob > b || (ob == b && oi < i)) { s = fmaxf(os, b); b = ob; i = oi; }
            else s = fmaxf(s, ob);
        }
        int grow = rowTile * BM + row;
        g_ind[grow] = i;
        if (b - s < MARGIN) {
            g_best[grow] = 0ull;
            int p = atomicAdd(&g_nflag, 1);
            g_flag[p] = grow;
        }
    }
}

// ---------------- #5 exact fp32 rescue: one item = (flagged row, 1/8 codebook) ----------------
__global__ void __launch_bounds__(256) rescue(const float* __restrict__ x,
                                              const float* __restrict__ embed) {
    __shared__ float4 xs[128];   // the row, 512 floats
    int tid = threadIdx.x;
    int w = tid >> 5, lane = tid & 31;
    int nitems = g_nflag * 8;
    for (int it = blockIdx.x; it < nitems; it += gridDim.x) {
        int row = g_flag[it >> 3];
        int slice = it & 7;
        __syncthreads();
        if (tid < 128) xs[tid] = *((const float4*)(x + (size_t)row * D) + tid);
        __syncthreads();
        float best = -3.4e38f;
        int bc = 0;
#pragma unroll
        for (int i = 0; i < 16; i++) {
            int c = slice * 128 + w * 16 + i;
            const float4* ep = (const float4*)(embed + (size_t)c * D);
            float dot = 0.0f;
#pragma unroll
            for (int p = 0; p < 4; p++) {
                float4 e = __ldg(ep + lane + p * 32);
                float4 xv = xs[lane + p * 32];
                dot = fmaf(xv.x, e.x, fmaf(xv.y, e.y,
                       fmaf(xv.z, e.z, fmaf(xv.w, e.w, dot))));
            }
#pragma unroll
            for (int off = 16; off; off >>= 1)
                dot += __shfl_xor_sync(0xffffffffu, dot, off);
            if (lane == 0) {
                float s = dot - g_e2h[c];
                if (s > best) { best = s; bc = c; }
            }
        }
        if (lane == 0) {
            unsigned bits = __float_as_uint(best);
            unsigned mono = (bits & 0x80000000u) ? ~bits : (bits | 0x80000000u);
            unsigned long long u = ((unsigned long long)mono << 32) | (unsigned)(~bc);
            atomicMax(&g_best[row], u);
        }
    }
}

// ---------------- #6 rescue finalize ----------------
__global__ void rescue_fin() {
    int i = blockIdx.x * blockDim.x + threadIdx.x;
    if (i < g_nflag) {
        int row = g_flag[i];
        g_ind[row] = (int)(~(unsigned)(g_best[row] & 0xffffffffull)) & 1023;
    }
}

// ---------------- #7 count rows (poslist + eind) ----------------
__global__ void count_rows(float* __restrict__ eind) {
    int row = blockIdx.x * blockDim.x + threadIdx.x;
    int k = g_ind[row];
    g_poslist[row] = atomicAdd(&g_cnt[k], 1);
    eind[row] = (float)k;
}

// ---------------- #8 scan + ema_cs fused ----------------
__global__ void scan_counts(const float* __restrict__ cluster_size,
                            float* __restrict__ ncs_out) {
    int k = threadIdx.x;
    __shared__ int s[1024];
    __shared__ float f[1024];
    int my = g_cnt[k];
    s[k] = my;
    __syncthreads();
#pragma unroll
    for (int off = 1; off < 1024; off <<= 1) {
        int v = (k >= off) ? s[k - off] : 0;
        __syncthreads();
        s[k] += v;
        __syncthreads();
    }
    g_off[k] = s[k] - my;
    float ncs = cluster_size[k] * DECAY + ONE_MINUS_DECAY * (float)my;
    ncs_out[k] = ncs;
    f[k] = ncs;
    __syncthreads();
#pragma unroll
    for (int st = 512; st > 0; st >>= 1) {
        if (k < st) f[k] += f[k + st];
        __syncthreads();
    }
    float n = f[0];
    g_cs[k] = (ncs + EPSF) / (n + (float)KCODES * EPSF) * n;
}

// ---------------- #9 fill rowlist ----------------
__global__ void fill_rowlist() {
    int row = blockIdx.x * blockDim.x + threadIdx.x;
    int k = g_ind[row];
    g_rowlist[g_off[k] + g_poslist[row]] = row;
}

// ---------------- #10 quant fill (row-parallel, skew-immune) ----------------
__global__ void __launch_bounds__(256) quant_fill(const float* __restrict__ embed,
                                                  float* __restrict__ quant) {
    int row = blockIdx.x * 2 + (threadIdx.x >> 7);
    int c = threadIdx.x & 127;
    int k = __ldg(&g_ind[row]);
    float4 e = __ldg((const float4*)(embed + (size_t)k * D) + c);
    *((float4*)(quant + (size_t)row * D) + c) = e;
}

// ---------------- #11 segmented embed_sum over rowlist chunks (skew-immune) ----------------
__global__ void __launch_bounds__(128) seg_sum(const float* __restrict__ x) {
    __shared__ int rows[CH];
    __shared__ int codes[CH];
    int t = threadIdx.x;
    int j0 = blockIdx.x * CH;
    if (t < CH) {
        int r = g_rowlist[j0 + t];
        rows[t] = r;
        codes[t] = g_ind[r];
    }
    __syncthreads();
    float4 acc = {0.f, 0.f, 0.f, 0.f};
#pragma unroll 4
    for (int j = 0; j < CH; j++) {
        float4 v = __ldg((const float4*)(x + (size_t)rows[j] * D) + t);
        acc.x += v.x; acc.y += v.y; acc.z += v.z; acc.w += v.w;
        if (j == CH - 1 || codes[j + 1] != codes[j]) {
            float* es = g_embed_sum + (size_t)codes[j] * D + t * 4;
            atomicAdd(es + 0, acc.x);
            atomicAdd(es + 1, acc.y);
            atomicAdd(es + 2, acc.z);
            atomicAdd(es + 3, acc.w);
            acc = make_float4(0.f, 0.f, 0.f, 0.f);
        }
    }
}

// ---------------- #12 EMA embed (flat) ----------------
__global__ void __launch_bounds__(256) ema_embed(const float* __restrict__ embed_avg,
                                                 float* __restrict__ nea_out,
                                                 float* __restrict__ ne_out) {
    int i = blockIdx.x * 256 + threadIdx.x;   // over KCODES*D/4 float4
    int c = (i * 4) >> 9;
    float4 es = *((const float4*)g_embed_sum + i);
    float4 ea = __ldg((const float4*)embed_avg + i);
    float inv = 1.0f / g_cs[c];
    float4 nea, ne;
    nea.x = ea.x * DECAY + ONE_MINUS_DECAY * es.x; ne.x = nea.x * inv;
    nea.y = ea.y * DECAY + ONE_MINUS_DECAY * es.y; ne.y = nea.y * inv;
    nea.z = ea.z * DECAY + ONE_MINUS_DECAY * es.z; ne.z = nea.z * inv;
    nea.w = ea.w * DECAY + ONE_MINUS_DECAY * es.w; ne.w = nea.w * inv;
    ((float4*)nea_out)[i] = nea;
    ((float4*)ne_out)[i] = ne;
}

// ---------------- launch ----------------
extern "C" void kernel_launch(void* const* d_in, const int* in_sizes, int n_in,
                              void* d_out, int out_size) {
    const float* x = (const float*)d_in[0];
    const float* embed = (const float*)d_in[1];
    const float* cluster_size = (const float*)d_in[2];
    const float* embed_avg = (const float*)d_in[3];

    float* out = (float*)d_out;
    float* quant = out;
    float* eind  = quant + (size_t)NROWS * D;
    float* ncs   = eind + NROWS;
    float* nea   = ncs + KCODES;
    float* ne    = nea + (size_t)KCODES * D;

    cudaFuncSetAttribute(gemm_hmma, cudaFuncAttributeMaxDynamicSharedMemorySize, SMEM_TOTAL);

    prep_b<<<KCODES, 256>>>(embed);                      // #1
    convert_x<<<1024, 256>>>(x, 0);                      // #2
    convert_x<<<1024, 256>>>(x, 1);                      // #3
    gemm_hmma<<<ROWTILES, 256, SMEM_TOTAL>>>();          // #4  <-- profile target
    rescue<<<4096, 256>>>(x, embed);                     // #5
    rescue_fin<<<16, 256>>>();                           // #6
    count_rows<<<NROWS / 256, 256>>>(eind);              // #7
    scan_counts<<<1, 1024>>>(cluster_size, ncs);         // #8
    fill_rowlist<<<NROWS / 256, 256>>>();                // #9
    quant_fill<<<NROWS / 2, 256>>>(embed, quant);        // #10
    seg_sum<<<NROWS / CH, 128>>>(x);                     // #11
    ema_embed<<<KCODES * D / 4 / 256, 256>>>(embed_avg, nea, ne);  // #12
}